// round 7
// baseline (speedup 1.0000x reference)
#include <cuda_runtime.h>
#include <math.h>
#include <stdint.h>

// Problem constants (fixed by the reference)
#define Bsz   4096
#define INDIM 1024
#define Dm    512
#define Nn    8
#define Ss    128
#define HOPS  4
#define TILEM 128     // token/GEMM block M tile
#define MAXT  40      // max token tiles per hop: 4096/128 + 8

#define A_ST 36       // A smem stride (fp32 words): frag banks (4*lr+lc) conflict-free
#define B_ST 72       // B smem stride (words): 72 mod 32 == 8 -> banks (8*lc+lr) conflict-free
// dynamic smem (words):
//   A stage s (fp32):    s*4608        [128][36]
//   B stage s (hi/lo):   9216 + s*4608 (hi [32][72] @ +0, lo @ +2304)
#define SMEM_WORDS 18432
#define SMEM_BYTES (SMEM_WORDS * 4)    // 73728

// -------- device scratch (no allocations allowed) --------
__device__ float g_z[Bsz * Dm];        // ping buffer (also holds z)
__device__ float g_buf[Bsz * Dm];      // pong buffer
__device__ float g_symmean[Bsz * Ss];
__device__ int   g_prog[Bsz * HOPS];
__device__ int   g_order[HOPS][Bsz];
__device__ int   g_tileE[HOPS][MAXT];
__device__ int   g_tileS[HOPS][MAXT];
__device__ int   g_tileC[HOPS][MAXT];
__device__ int   g_numTiles[HOPS];
// pre-split tf32 hi/lo weights
__device__ uint32_t g_WinH[INDIM * Dm],  g_WinL[INDIM * Dm];
__device__ uint32_t g_symWH[Nn * Dm * Ss], g_symWL[Nn * Dm * Ss];
__device__ uint32_t g_opsWH[Nn * Dm * Dm], g_opsWL[Nn * Dm * Dm];

__device__ __forceinline__ float gelu_tanh(float x) {
    float x3 = x * x * x;
    return 0.5f * x * (1.0f + tanhf(0.7978845608028654f * (x + 0.044715f * x3)));
}

// ---------------- 3xTF32 helpers ----------------
__device__ __forceinline__ uint32_t f2tf(float v) {
    uint32_t r; asm("cvt.rna.tf32.f32 %0, %1;" : "=r"(r) : "f"(v)); return r;
}
__device__ __forceinline__ void split1(float a, uint32_t& h, uint32_t& l) {
    h = f2tf(a);
    l = f2tf(__fsub_rn(a, __uint_as_float(h)));
}
__device__ __forceinline__ void split4(float4 v, uint4& h, uint4& l) {
    split1(v.x, h.x, l.x); split1(v.y, h.y, l.y);
    split1(v.z, h.z, l.z); split1(v.w, h.w, l.w);
}

#define MMA(d, a, b)                                                          \
    asm("mma.sync.aligned.m16n8k8.row.col.f32.tf32.tf32.f32 "                 \
        "{%0,%1,%2,%3}, {%4,%5,%6,%7}, {%8,%9}, {%0,%1,%2,%3};"               \
        : "+f"(d[0]), "+f"(d[1]), "+f"(d[2]), "+f"(d[3])                      \
        : "r"(a[0]), "r"(a[1]), "r"(a[2]), "r"(a[3]), "r"(b[0]), "r"(b[1]))

// ---------------- cp.async helpers ----------------
__device__ __forceinline__ void cp_async16(uint32_t saddr, const void* g) {
    asm volatile("cp.async.cg.shared.global [%0], [%1], 16;" :: "r"(saddr), "l"(g));
}
__device__ __forceinline__ void cp_async16_z(uint32_t saddr, const void* g, int srcsz) {
    asm volatile("cp.async.cg.shared.global [%0], [%1], 16, %2;"
                 :: "r"(saddr), "l"(g), "r"(srcsz));
}
#define CP_COMMIT() asm volatile("cp.async.commit_group;")
#define CP_WAIT0()  asm volatile("cp.async.wait_group 0;" ::: "memory")

// Stage A slab (128 rows x 32 k, raw fp32) into stage s.
__device__ __forceinline__ void stage_A_rows(uint32_t* smem, int s,
                                             const float* __restrict__ g,
                                             size_t row0, int ldA, int kcol, int tid) {
    uint32_t base = (uint32_t)__cvta_generic_to_shared(smem + s * 4608);
    const int r = tid >> 3, col = (tid & 7) * 4;
#pragma unroll
    for (int i = 0; i < 8; i++) {
        int row = i * 16 + r;
        cp_async16(base + (uint32_t)(row * A_ST + col) * 4,
                   g + (row0 + row) * ldA + kcol + col);
    }
}

// Stage B slab (32 k x 64 n, pre-split hi/lo) into stage s.
__device__ __forceinline__ void stage_B(uint32_t* smem, int s,
                                        const uint32_t* __restrict__ GH,
                                        const uint32_t* __restrict__ GL,
                                        size_t gbase, int ldB, int tid) {
    uint32_t base_h = (uint32_t)__cvta_generic_to_shared(smem + 9216 + s * 4608);
    uint32_t base_l = base_h + 2304 * 4;
#pragma unroll
    for (int p = 0; p < 4; p++) {
        int q = tid + p * 128;
        int row = q >> 4, col = (q & 15) * 4;
        uint32_t soff = (uint32_t)(row * B_ST + col) * 4;
        size_t goff = gbase + (size_t)row * ldB + col;
        cp_async16(base_h + soff, GH + goff);
        cp_async16(base_l + soff, GL + goff);
    }
}

// One k8 step: warp (wm,wn) computes 64x32 with 3xTF32 (4 m-tiles x 4 n-tiles).
// A read as fp32 from smem, split to hi/lo in registers.
__device__ __forceinline__ void mma_k8f(
    const float* __restrict__ As, const uint32_t* __restrict__ Bh,
    const uint32_t* __restrict__ Bl, int wm, int wn, int lane, int k8,
    float acc[4][4][4]) {
    const int lr = lane >> 2, lc = lane & 3;
    uint32_t ah[4][4], al[4][4];
#pragma unroll
    for (int mt = 0; mt < 4; mt++) {
        int m = wm * 64 + mt * 16 + lr;
        float a0 = As[m * A_ST + k8 + lc];
        float a1 = As[(m + 8) * A_ST + k8 + lc];
        float a2 = As[m * A_ST + k8 + lc + 4];
        float a3 = As[(m + 8) * A_ST + k8 + lc + 4];
        split1(a0, ah[mt][0], al[mt][0]);
        split1(a1, ah[mt][1], al[mt][1]);
        split1(a2, ah[mt][2], al[mt][2]);
        split1(a3, ah[mt][3], al[mt][3]);
    }
#pragma unroll
    for (int nt = 0; nt < 4; nt++) {
        int n = wn * 32 + nt * 8 + lr;
        uint32_t bh[2], bl[2];
        bh[0] = Bh[(k8 + lc) * B_ST + n];
        bh[1] = Bh[(k8 + lc + 4) * B_ST + n];
        bl[0] = Bl[(k8 + lc) * B_ST + n];
        bl[1] = Bl[(k8 + lc + 4) * B_ST + n];
#pragma unroll
        for (int mt = 0; mt < 4; mt++) {
            MMA(acc[mt][nt], ah[mt], bl);
            MMA(acc[mt][nt], al[mt], bh);
            MMA(acc[mt][nt], ah[mt], bh);
        }
    }
}

// ============ weight pre-split (once per launch; bit-identical split) ====
__global__ void split_sel(const float* __restrict__ src, int sel, int n4) {
    int i = blockIdx.x * blockDim.x + threadIdx.x;
    if (i >= n4) return;
    uint32_t* hi = (sel == 0) ? g_WinH : (sel == 1) ? g_symWH : g_opsWH;
    uint32_t* lo = (sel == 0) ? g_WinL : (sel == 1) ? g_symWL : g_opsWL;
    float4 v = reinterpret_cast<const float4*>(src)[i];
    uint4 h, l; split4(v, h, l);
    reinterpret_cast<uint4*>(hi)[i] = h;
    reinterpret_cast<uint4*>(lo)[i] = l;
}

// ============ GEMM 1: z = x @ W_in + b_in  (block 128x64, warp 64x32) ============
__global__ __launch_bounds__(128) void gemm_z_tc(
    const float* __restrict__ A, const float* __restrict__ bias) {
    extern __shared__ uint32_t smem[];
    const int tid = threadIdx.x, lane = tid & 31, warp = tid >> 5;
    const int wm = warp & 1, wn = warp >> 1;
    const size_t bm = blockIdx.x * TILEM;
    const int bn = blockIdx.y * 64;
    float acc[4][4][4] = {};
    stage_A_rows(smem, 0, A, bm, INDIM, 0, tid);
    stage_B(smem, 0, g_WinH, g_WinL, (size_t)bn, Dm, tid);
    CP_COMMIT();
    for (int k0 = 0; k0 < INDIM; k0 += 32) {
        const int s = (k0 >> 5) & 1;
        CP_WAIT0();
        __syncthreads();
        if (k0 + 32 < INDIM) {
            stage_A_rows(smem, s ^ 1, A, bm, INDIM, k0 + 32, tid);
            stage_B(smem, s ^ 1, g_WinH, g_WinL, (size_t)(k0 + 32) * Dm + bn, Dm, tid);
        }
        CP_COMMIT();
        const float* As = reinterpret_cast<const float*>(smem + s * 4608);
        const uint32_t* Bh = smem + 9216 + s * 4608;
        const uint32_t* Bl = Bh + 2304;
        mma_k8f(As, Bh, Bl, wm, wn, lane, 0, acc);
        mma_k8f(As, Bh, Bl, wm, wn, lane, 8, acc);
        mma_k8f(As, Bh, Bl, wm, wn, lane, 16, acc);
        mma_k8f(As, Bh, Bl, wm, wn, lane, 24, acc);
        __syncthreads();
    }
    const int lr = lane >> 2, lc = lane & 3;
#pragma unroll
    for (int mt = 0; mt < 4; mt++)
#pragma unroll
        for (int nt = 0; nt < 4; nt++) {
            size_t m0 = bm + wm * 64 + mt * 16 + lr;
            int n0 = bn + wn * 32 + nt * 8 + 2 * lc;
            float b0 = bias[n0], b1 = bias[n0 + 1];
            g_z[m0 * Dm + n0]           = acc[mt][nt][0] + b0;
            g_z[m0 * Dm + n0 + 1]       = acc[mt][nt][1] + b1;
            g_z[(m0 + 8) * Dm + n0]     = acc[mt][nt][2] + b0;
            g_z[(m0 + 8) * Dm + n0 + 1] = acc[mt][nt][3] + b1;
        }
}

// ======= GEMM 2: sym[b, n*128+s] = sum_d z[b,d]*sym_W[n,d,s] =======
__global__ __launch_bounds__(128) void gemm_sym_tc(float* __restrict__ symOut) {
    extern __shared__ uint32_t smem[];
    const int tid = threadIdx.x, lane = tid & 31, warp = tid >> 5;
    const int wm = warp & 1, wn = warp >> 1;
    const size_t bm = blockIdx.x * TILEM;
    const int bn = blockIdx.y * 64;
    const size_t boff = (size_t)(bn >> 7) * (Dm * Ss) + (bn & 127);
    float acc[4][4][4] = {};
    stage_A_rows(smem, 0, g_z, bm, Dm, 0, tid);
    stage_B(smem, 0, g_symWH, g_symWL, boff, Ss, tid);
    CP_COMMIT();
    for (int k0 = 0; k0 < Dm; k0 += 32) {
        const int s = (k0 >> 5) & 1;
        CP_WAIT0();
        __syncthreads();
        if (k0 + 32 < Dm) {
            stage_A_rows(smem, s ^ 1, g_z, bm, Dm, k0 + 32, tid);
            stage_B(smem, s ^ 1, g_symWH, g_symWL, boff + (size_t)(k0 + 32) * Ss, Ss, tid);
        }
        CP_COMMIT();
        const float* As = reinterpret_cast<const float*>(smem + s * 4608);
        const uint32_t* Bh = smem + 9216 + s * 4608;
        const uint32_t* Bl = Bh + 2304;
        mma_k8f(As, Bh, Bl, wm, wn, lane, 0, acc);
        mma_k8f(As, Bh, Bl, wm, wn, lane, 8, acc);
        mma_k8f(As, Bh, Bl, wm, wn, lane, 16, acc);
        mma_k8f(As, Bh, Bl, wm, wn, lane, 24, acc);
        __syncthreads();
    }
    const int lr = lane >> 2, lc = lane & 3;
#pragma unroll
    for (int mt = 0; mt < 4; mt++)
#pragma unroll
        for (int nt = 0; nt < 4; nt++) {
            size_t m0 = bm + wm * 64 + mt * 16 + lr;
            int n0 = bn + wn * 32 + nt * 8 + 2 * lc;
            symOut[m0 * (Nn * Ss) + n0]           = acc[mt][nt][0];
            symOut[m0 * (Nn * Ss) + n0 + 1]       = acc[mt][nt][1];
            symOut[(m0 + 8) * (Nn * Ss) + n0]     = acc[mt][nt][2];
            symOut[(m0 + 8) * (Nn * Ss) + n0 + 1] = acc[mt][nt][3];
        }
}

// ================== symmean[b,s] = mean_n sym[b,n,s] ==================
__global__ void mean_kernel(const float* __restrict__ symOut) {
    int i = blockIdx.x * blockDim.x + threadIdx.x;
    int b = i >> 7, s = i & 127;
    const float* p = symOut + (size_t)b * (Nn * Ss) + s;
    float sum = 0.f;
#pragma unroll
    for (int n = 0; n < Nn; n++) sum += p[n * Ss];
    g_symmean[i] = sum * 0.125f;
}

// ====== router: compensated-fp32 logits + argmax -> prog (frozen since R3) ======
__global__ __launch_bounds__(288) void router_kernel(
    const float* __restrict__ RW, const float* __restrict__ rb, float* __restrict__ progf) {
    __shared__ float rin[8][644];
    __shared__ float lg[8][36];
    const int b0 = blockIdx.x * 8;
    const int tid = threadIdx.x;
    for (int i = tid; i < 8 * 640; i += 288) {
        int t = i / 640, k = i - t * 640;
        rin[t][k] = (k < Dm) ? g_z[(size_t)(b0 + t) * Dm + k]
                             : g_symmean[(size_t)(b0 + t) * Ss + (k - Dm)];
    }
    __syncthreads();
    {
        const int t = tid / 36, j = tid - t * 36;
        const float* rw = RW + j;
        float s[4] = {0.f, 0.f, 0.f, 0.f};
        float c[4] = {0.f, 0.f, 0.f, 0.f};
#pragma unroll 2
        for (int k = 0; k < 640; k += 4) {
#pragma unroll
            for (int i = 0; i < 4; i++) {
                float x = rin[t][k + i];
                float w = __ldg(&rw[(k + i) * 36]);
                float p = __fmul_rn(x, w);
                float e = __fmaf_rn(x, w, -p);
                float t1  = __fadd_rn(s[i], p);
                float bb  = __fsub_rn(t1, s[i]);
                float er1 = __fadd_rn(__fsub_rn(s[i], __fsub_rn(t1, bb)),
                                      __fsub_rn(p, bb));
                s[i] = t1;
                c[i] = __fadd_rn(c[i], __fadd_rn(er1, e));
            }
        }
        float S = rb[j], C = 0.f;
#pragma unroll
        for (int i = 0; i < 4; i++) {
            float t1  = __fadd_rn(S, s[i]);
            float bb  = __fsub_rn(t1, S);
            float er1 = __fadd_rn(__fsub_rn(S, __fsub_rn(t1, bb)),
                                  __fsub_rn(s[i], bb));
            S = t1;
            C = __fadd_rn(C, __fadd_rn(er1, c[i]));
        }
        lg[t][j] = __fadd_rn(S, C);
    }
    __syncthreads();
    if (tid < 32) {
        int t = tid >> 2, h = tid & 3;
        const float* l = &lg[t][h * 9];
        float best = l[0]; int bi = 0;
#pragma unroll
        for (int j = 1; j < 9; j++)
            if (l[j] > best) { best = l[j]; bi = j; }
        g_prog[(b0 + t) * HOPS + h] = bi;
        progf[(b0 + t) * HOPS + h] = (float)bi;
    }
}

// ======= schedule: group active tokens by (hop, expert); 128-row tiles =======
__global__ void schedule_kernel() {
    __shared__ int cnt[HOPS][Nn];
    __shared__ int cur[HOPS][Nn];
    const int tid = threadIdx.x;
    if (tid < HOPS * Nn) cnt[tid / Nn][tid % Nn] = 0;
    __syncthreads();
    for (int b = tid; b < Bsz; b += blockDim.x) {
        bool act = true;
        for (int t = 0; t < HOPS; t++) {
            int e = g_prog[b * HOPS + t];
            act = act && (e != Nn);
            if (act) atomicAdd(&cnt[t][e], 1);
        }
    }
    __syncthreads();
    if (tid < HOPS) {
        int t = tid, p = 0, nt = 0;
        for (int e = 0; e < Nn; e++) {
            cur[t][e] = p;
            int c = cnt[t][e], q = p;
            while (c > 0) {
                g_tileE[t][nt] = e; g_tileS[t][nt] = q;
                g_tileC[t][nt] = (c < TILEM) ? c : TILEM;
                q += TILEM; c -= TILEM; nt++;
            }
            p += cnt[t][e];
        }
        g_numTiles[t] = nt;
    }
    __syncthreads();
    for (int b = tid; b < Bsz; b += blockDim.x) {
        bool act = true;
        for (int t = 0; t < HOPS; t++) {
            int e = g_prog[b * HOPS + t];
            act = act && (e != Nn);
            if (act) { int p = atomicAdd(&cur[t][e], 1); g_order[t][p] = b; }
        }
    }
}

// == hop: dst[tok] = gelu(src[tok] @ ops_W[e] + ops_b[e]); gather via cp.async ==
// No inter-hop copies: active(h+1) ⊆ active(h).
__global__ __launch_bounds__(128) void hop_tc(
    int hop, int srcSel, const float* __restrict__ opsB) {
    if ((int)blockIdx.x >= g_numTiles[hop]) return;
    extern __shared__ uint32_t smem[];
    __shared__ int toks[TILEM];
    const float* src = (srcSel == 0) ? g_z : g_buf;
    float* dst = (srcSel == 0) ? g_buf : g_z;
    const int e     = g_tileE[hop][blockIdx.x];
    const int start = g_tileS[hop][blockIdx.x];
    const int cnt   = g_tileC[hop][blockIdx.x];
    const int bn    = blockIdx.y * 64;
    const int tid = threadIdx.x, lane = tid & 31, warp = tid >> 5;
    const int wm = warp & 1, wn = warp >> 1;
    toks[tid] = (tid < cnt) ? g_order[hop][start + tid] : -1;
    __syncthreads();
    const uint32_t* WH = g_opsWH + (size_t)e * (Dm * Dm);
    const uint32_t* WL = g_opsWL + (size_t)e * (Dm * Dm);
    // gather-stage A rows (zero-fill padding rows)
    const int r = tid >> 3, colq = (tid & 7) * 4;
    int myTok[8];
#pragma unroll
    for (int i = 0; i < 8; i++) myTok[i] = toks[i * 16 + r];
    {
        uint32_t base = (uint32_t)__cvta_generic_to_shared(smem);
#pragma unroll
        for (int i = 0; i < 8; i++) {
            int row = i * 16 + r;
            int tk = myTok[i] < 0 ? 0 : myTok[i];
            cp_async16_z(base + (uint32_t)(row * A_ST + colq) * 4,
                         src + (size_t)tk * Dm + colq, myTok[i] >= 0 ? 16 : 0);
        }
    }
    stage_B(smem, 0, WH, WL, (size_t)bn, Dm, tid);
    CP_COMMIT();
    float acc[4][4][4] = {};
    for (int k0 = 0; k0 < Dm; k0 += 32) {
        const int s = (k0 >> 5) & 1;
        CP_WAIT0();
        __syncthreads();
        if (k0 + 32 < Dm) {
            uint32_t base = (uint32_t)__cvta_generic_to_shared(smem + (s ^ 1) * 4608);
#pragma unroll
            for (int i = 0; i < 8; i++) {
                int row = i * 16 + r;
                int tk = myTok[i] < 0 ? 0 : myTok[i];
                cp_async16_z(base + (uint32_t)(row * A_ST + colq) * 4,
                             src + (size_t)tk * Dm + k0 + 32 + colq, myTok[i] >= 0 ? 16 : 0);
            }
            stage_B(smem, s ^ 1, WH, WL, (size_t)(k0 + 32) * Dm + bn, Dm, tid);
        }
        CP_COMMIT();
        const float* As = reinterpret_cast<const float*>(smem + s * 4608);
        const uint32_t* Bh = smem + 9216 + s * 4608;
        const uint32_t* Bl = Bh + 2304;
        mma_k8f(As, Bh, Bl, wm, wn, lane, 0, acc);
        mma_k8f(As, Bh, Bl, wm, wn, lane, 8, acc);
        mma_k8f(As, Bh, Bl, wm, wn, lane, 16, acc);
        mma_k8f(As, Bh, Bl, wm, wn, lane, 24, acc);
        __syncthreads();
    }
    const int lr = lane >> 2, lc = lane & 3;
#pragma unroll
    for (int mt = 0; mt < 4; mt++) {
        int r0 = wm * 64 + mt * 16 + lr;
        int tk0 = toks[r0], tk1 = toks[r0 + 8];
#pragma unroll
        for (int nt = 0; nt < 4; nt++) {
            int n0 = bn + wn * 32 + nt * 8 + 2 * lc;
            float b0 = opsB[e * Dm + n0], b1 = opsB[e * Dm + n0 + 1];
            if (tk0 >= 0) {
                dst[(size_t)tk0 * Dm + n0]     = gelu_tanh(acc[mt][nt][0] + b0);
                dst[(size_t)tk0 * Dm + n0 + 1] = gelu_tanh(acc[mt][nt][1] + b1);
            }
            if (tk1 >= 0) {
                dst[(size_t)tk1 * Dm + n0]     = gelu_tanh(acc[mt][nt][2] + b0);
                dst[(size_t)tk1 * Dm + n0 + 1] = gelu_tanh(acc[mt][nt][3] + b1);
            }
        }
    }
}

// ===== final gather: out[b] = buffer holding b's value after its last active hop =====
__global__ void gather_out(float* __restrict__ out) {
    int idx = blockIdx.x * blockDim.x + threadIdx.x;   // over Bsz*Dm/4 float4s
    int b = idx >> 7;
    int nact = 0;
#pragma unroll
    for (int t = 0; t < HOPS; t++) {
        if (g_prog[b * HOPS + t] == Nn) break;
        nact++;
    }
    const float* src = (nact & 1) ? g_buf : g_z;
    reinterpret_cast<float4*>(out)[idx] = reinterpret_cast<const float4*>(src)[idx];
}

// =========================== launch ===========================
extern "C" void kernel_launch(void* const* d_in, const int* in_sizes, int n_in,
                              void* d_out, int out_size) {
    const float* x        = (const float*)d_in[0];
    const float* W_in     = (const float*)d_in[1];
    const float* b_in     = (const float*)d_in[2];
    const float* ops_W    = (const float*)d_in[3];
    const float* ops_b    = (const float*)d_in[4];
    const float* sym_W    = (const float*)d_in[5];
    const float* router_W = (const float*)d_in[6];
    const float* router_b = (const float*)d_in[7];
    (void)in_sizes; (void)n_in; (void)out_size;

    float* out   = (float*)d_out;                 // [B, D]
    float* progf = out + Bsz * Dm;                // [B, HOPS] as float
    float* sym   = progf + Bsz * HOPS;            // [B, N, S]

    cudaFuncSetAttribute(gemm_z_tc,   cudaFuncAttributeMaxDynamicSharedMemorySize, SMEM_BYTES);
    cudaFuncSetAttribute(gemm_sym_tc, cudaFuncAttributeMaxDynamicSharedMemorySize, SMEM_BYTES);
    cudaFuncSetAttribute(hop_tc,      cudaFuncAttributeMaxDynamicSharedMemorySize, SMEM_BYTES);

    // pre-split weights into tf32 hi/lo
    split_sel<<<(INDIM * Dm / 4 + 255) / 256, 256>>>(W_in, 0, INDIM * Dm / 4);
    split_sel<<<(Nn * Dm * Ss / 4 + 255) / 256, 256>>>(sym_W, 1, Nn * Dm * Ss / 4);
    split_sel<<<(Nn * Dm * Dm / 4 + 255) / 256, 256>>>(ops_W, 2, Nn * Dm * Dm / 4);

    gemm_z_tc   <<<dim3(Bsz / TILEM, Dm / 64), 128, SMEM_BYTES>>>(x, b_in);
    gemm_sym_tc <<<dim3(Bsz / TILEM, (Nn * Ss) / 64), 128, SMEM_BYTES>>>(sym);
    mean_kernel <<<(Bsz * Ss) / 256, 256>>>(sym);
    router_kernel<<<Bsz / 8, 288>>>(router_W, router_b, progf);
    schedule_kernel<<<1, 512>>>();

    hop_tc<<<dim3(MAXT, Dm / 64), 128, SMEM_BYTES>>>(0, 0, ops_b);  // z   -> buf
    hop_tc<<<dim3(MAXT, Dm / 64), 128, SMEM_BYTES>>>(1, 1, ops_b);  // buf -> z
    hop_tc<<<dim3(MAXT, Dm / 64), 128, SMEM_BYTES>>>(2, 0, ops_b);  // z   -> buf
    hop_tc<<<dim3(MAXT, Dm / 64), 128, SMEM_BYTES>>>(3, 1, ops_b);  // buf -> z

    gather_out<<<(Bsz * Dm / 4) / 256, 256>>>(out);
}

// round 8
// speedup vs baseline: 1.0057x; 1.0057x over previous
#include <cuda_runtime.h>
#include <math.h>
#include <stdint.h>

// Problem constants (fixed by the reference)
#define Bsz   4096
#define INDIM 1024
#define Dm    512
#define Nn    8
#define Ss    128
#define HOPS  4
#define TILEM 64      // token/GEMM block M tile
#define MAXT  72      // max token tiles per hop: 4096/64 + 8

#define A_ST 36       // A smem stride (fp32 words): frag banks (4*lr+lc) conflict-free
#define B_ST 72       // B smem stride (words): 72 mod 32 == 8 -> banks (8*lc+lr) conflict-free
// dynamic smem (words):
//   A stage s (fp32):  s*2304        [64][36]
//   B stage s (hi/lo): 4608 + s*4608 (hi [32][72] @ +0, lo @ +2304)
#define SMEM_WORDS 13824
#define SMEM_BYTES (SMEM_WORDS * 4)    // 55296

// -------- device scratch (no allocations allowed) --------
__device__ float g_z[Bsz * Dm];        // ping buffer (also holds z)
__device__ float g_buf[Bsz * Dm];      // pong buffer
__device__ float g_symmean[Bsz * Ss];
__device__ int   g_prog[Bsz * HOPS];
__device__ int   g_order[HOPS][Bsz];
__device__ int   g_tileE[HOPS][MAXT];
__device__ int   g_tileS[HOPS][MAXT];
__device__ int   g_tileC[HOPS][MAXT];
__device__ int   g_numTiles[HOPS];
// pre-split tf32 hi/lo weights
__device__ uint32_t g_WinH[INDIM * Dm],  g_WinL[INDIM * Dm];
__device__ uint32_t g_symWH[Nn * Dm * Ss], g_symWL[Nn * Dm * Ss];
__device__ uint32_t g_opsWH[Nn * Dm * Dm], g_opsWL[Nn * Dm * Dm];

__device__ __forceinline__ float gelu_tanh(float x) {
    float x3 = x * x * x;
    return 0.5f * x * (1.0f + tanhf(0.7978845608028654f * (x + 0.044715f * x3)));
}

// ---------------- 3xTF32 helpers ----------------
__device__ __forceinline__ uint32_t f2tf(float v) {
    uint32_t r; asm("cvt.rna.tf32.f32 %0, %1;" : "=r"(r) : "f"(v)); return r;
}
__device__ __forceinline__ void split1(float a, uint32_t& h, uint32_t& l) {
    h = f2tf(a);
    l = f2tf(__fsub_rn(a, __uint_as_float(h)));
}
__device__ __forceinline__ void split4(float4 v, uint4& h, uint4& l) {
    split1(v.x, h.x, l.x); split1(v.y, h.y, l.y);
    split1(v.z, h.z, l.z); split1(v.w, h.w, l.w);
}
// exact TwoSum
__device__ __forceinline__ void two_sum(float a, float b, float& s, float& e) {
    s = __fadd_rn(a, b);
    float bv = __fsub_rn(s, a);
    e = __fadd_rn(__fsub_rn(a, __fsub_rn(s, bv)), __fsub_rn(b, bv));
}

#define MMA(d, a, b)                                                          \
    asm("mma.sync.aligned.m16n8k8.row.col.f32.tf32.tf32.f32 "                 \
        "{%0,%1,%2,%3}, {%4,%5,%6,%7}, {%8,%9}, {%0,%1,%2,%3};"               \
        : "+f"(d[0]), "+f"(d[1]), "+f"(d[2]), "+f"(d[3])                      \
        : "r"(a[0]), "r"(a[1]), "r"(a[2]), "r"(a[3]), "r"(b[0]), "r"(b[1]))

// ---------------- cp.async helpers ----------------
__device__ __forceinline__ void cp_async16(uint32_t saddr, const void* g) {
    asm volatile("cp.async.cg.shared.global [%0], [%1], 16;" :: "r"(saddr), "l"(g));
}
__device__ __forceinline__ void cp_async16_z(uint32_t saddr, const void* g, int srcsz) {
    asm volatile("cp.async.cg.shared.global [%0], [%1], 16, %2;"
                 :: "r"(saddr), "l"(g), "r"(srcsz));
}
#define CP_COMMIT() asm volatile("cp.async.commit_group;")
#define CP_WAIT0()  asm volatile("cp.async.wait_group 0;" ::: "memory")

// Stage A slab (64 rows x 32 k, raw fp32) into stage s. 64 threads.
__device__ __forceinline__ void stage_A64(uint32_t* smem, int s,
                                          const float* __restrict__ g,
                                          size_t row0, int ldA, int kcol, int tid) {
    uint32_t base = (uint32_t)__cvta_generic_to_shared(smem + s * 2304);
    const int r = tid >> 3, col = (tid & 7) * 4;
#pragma unroll
    for (int i = 0; i < 8; i++) {
        int row = i * 8 + r;
        cp_async16(base + (uint32_t)(row * A_ST + col) * 4,
                   g + (row0 + row) * ldA + kcol + col);
    }
}

// Stage B slab (32 k x 64 n, pre-split hi/lo) into stage s. 64 threads.
__device__ __forceinline__ void stage_B64(uint32_t* smem, int s,
                                          const uint32_t* __restrict__ GH,
                                          const uint32_t* __restrict__ GL,
                                          size_t gbase, int ldB, int tid) {
    uint32_t base_h = (uint32_t)__cvta_generic_to_shared(smem + 4608 + s * 4608);
    uint32_t base_l = base_h + 2304 * 4;
#pragma unroll
    for (int p = 0; p < 8; p++) {
        int q = tid + p * 64;
        int row = q >> 4, col = (q & 15) * 4;
        uint32_t soff = (uint32_t)(row * B_ST + col) * 4;
        size_t goff = gbase + (size_t)row * ldB + col;
        cp_async16(base_h + soff, GH + goff);
        cp_async16(base_l + soff, GL + goff);
    }
}

// One k8 step: warp wn computes 64x32 with 3xTF32 (4 m-tiles x 4 n-tiles).
// A read as fp32 from smem, split to hi/lo in registers.
__device__ __forceinline__ void mma_k8f(
    const float* __restrict__ As, const uint32_t* __restrict__ Bh,
    const uint32_t* __restrict__ Bl, int wn, int lane, int k8,
    float acc[4][4][4]) {
    const int lr = lane >> 2, lc = lane & 3;
    uint32_t ah[4][4], al[4][4];
#pragma unroll
    for (int mt = 0; mt < 4; mt++) {
        int m = mt * 16 + lr;
        float a0 = As[m * A_ST + k8 + lc];
        float a1 = As[(m + 8) * A_ST + k8 + lc];
        float a2 = As[m * A_ST + k8 + lc + 4];
        float a3 = As[(m + 8) * A_ST + k8 + lc + 4];
        split1(a0, ah[mt][0], al[mt][0]);
        split1(a1, ah[mt][1], al[mt][1]);
        split1(a2, ah[mt][2], al[mt][2]);
        split1(a3, ah[mt][3], al[mt][3]);
    }
#pragma unroll
    for (int nt = 0; nt < 4; nt++) {
        int n = wn * 32 + nt * 8 + lr;
        uint32_t bh[2], bl[2];
        bh[0] = Bh[(k8 + lc) * B_ST + n];
        bh[1] = Bh[(k8 + lc + 4) * B_ST + n];
        bl[0] = Bl[(k8 + lc) * B_ST + n];
        bl[1] = Bl[(k8 + lc + 4) * B_ST + n];
#pragma unroll
        for (int mt = 0; mt < 4; mt++) {
            MMA(acc[mt][nt], ah[mt], bl);
            MMA(acc[mt][nt], al[mt], bh);
            MMA(acc[mt][nt], ah[mt], bh);
        }
    }
}

// ============ weight pre-split (once per launch; bit-identical split) ====
__global__ void split_sel(const float* __restrict__ src, int sel, int n4) {
    int i = blockIdx.x * blockDim.x + threadIdx.x;
    if (i >= n4) return;
    uint32_t* hi = (sel == 0) ? g_WinH : (sel == 1) ? g_symWH : g_opsWH;
    uint32_t* lo = (sel == 0) ? g_WinL : (sel == 1) ? g_symWL : g_opsWL;
    float4 v = reinterpret_cast<const float4*>(src)[i];
    uint4 h, l; split4(v, h, l);
    reinterpret_cast<uint4*>(hi)[i] = h;
    reinterpret_cast<uint4*>(lo)[i] = l;
}

// ============ GEMM 1: z = x @ W_in + b_in  (block 64x64, 2 warps of 64x32) ============
__global__ __launch_bounds__(64) void gemm_z_tc(
    const float* __restrict__ A, const float* __restrict__ bias) {
    extern __shared__ uint32_t smem[];
    const int tid = threadIdx.x, lane = tid & 31, wn = tid >> 5;
    const size_t bm = blockIdx.x * TILEM;
    const int bn = blockIdx.y * 64;
    float acc[4][4][4] = {};
    stage_A64(smem, 0, A, bm, INDIM, 0, tid);
    stage_B64(smem, 0, g_WinH, g_WinL, (size_t)bn, Dm, tid);
    CP_COMMIT();
    for (int k0 = 0; k0 < INDIM; k0 += 32) {
        const int s = (k0 >> 5) & 1;
        CP_WAIT0();
        __syncthreads();
        if (k0 + 32 < INDIM) {
            stage_A64(smem, s ^ 1, A, bm, INDIM, k0 + 32, tid);
            stage_B64(smem, s ^ 1, g_WinH, g_WinL, (size_t)(k0 + 32) * Dm + bn, Dm, tid);
        }
        CP_COMMIT();
        const float* As = reinterpret_cast<const float*>(smem + s * 2304);
        const uint32_t* Bh = smem + 4608 + s * 4608;
        const uint32_t* Bl = Bh + 2304;
        mma_k8f(As, Bh, Bl, wn, lane, 0, acc);
        mma_k8f(As, Bh, Bl, wn, lane, 8, acc);
        mma_k8f(As, Bh, Bl, wn, lane, 16, acc);
        mma_k8f(As, Bh, Bl, wn, lane, 24, acc);
        __syncthreads();
    }
    const int lr = lane >> 2, lc = lane & 3;
#pragma unroll
    for (int mt = 0; mt < 4; mt++)
#pragma unroll
        for (int nt = 0; nt < 4; nt++) {
            size_t m0 = bm + mt * 16 + lr;
            int n0 = bn + wn * 32 + nt * 8 + 2 * lc;
            float b0 = bias[n0], b1 = bias[n0 + 1];
            g_z[m0 * Dm + n0]           = acc[mt][nt][0] + b0;
            g_z[m0 * Dm + n0 + 1]       = acc[mt][nt][1] + b1;
            g_z[(m0 + 8) * Dm + n0]     = acc[mt][nt][2] + b0;
            g_z[(m0 + 8) * Dm + n0 + 1] = acc[mt][nt][3] + b1;
        }
}

// ======= GEMM 2: sym[b, n*128+s] = sum_d z[b,d]*sym_W[n,d,s] =======
__global__ __launch_bounds__(64) void gemm_sym_tc(float* __restrict__ symOut) {
    extern __shared__ uint32_t smem[];
    const int tid = threadIdx.x, lane = tid & 31, wn = tid >> 5;
    const size_t bm = blockIdx.x * TILEM;
    const int bn = blockIdx.y * 64;
    const size_t boff = (size_t)(bn >> 7) * (Dm * Ss) + (bn & 127);
    float acc[4][4][4] = {};
    stage_A64(smem, 0, g_z, bm, Dm, 0, tid);
    stage_B64(smem, 0, g_symWH, g_symWL, boff, Ss, tid);
    CP_COMMIT();
    for (int k0 = 0; k0 < Dm; k0 += 32) {
        const int s = (k0 >> 5) & 1;
        CP_WAIT0();
        __syncthreads();
        if (k0 + 32 < Dm) {
            stage_A64(smem, s ^ 1, g_z, bm, Dm, k0 + 32, tid);
            stage_B64(smem, s ^ 1, g_symWH, g_symWL, boff + (size_t)(k0 + 32) * Ss, Ss, tid);
        }
        CP_COMMIT();
        const float* As = reinterpret_cast<const float*>(smem + s * 2304);
        const uint32_t* Bh = smem + 4608 + s * 4608;
        const uint32_t* Bl = Bh + 2304;
        mma_k8f(As, Bh, Bl, wn, lane, 0, acc);
        mma_k8f(As, Bh, Bl, wn, lane, 8, acc);
        mma_k8f(As, Bh, Bl, wn, lane, 16, acc);
        mma_k8f(As, Bh, Bl, wn, lane, 24, acc);
        __syncthreads();
    }
    const int lr = lane >> 2, lc = lane & 3;
#pragma unroll
    for (int mt = 0; mt < 4; mt++)
#pragma unroll
        for (int nt = 0; nt < 4; nt++) {
            size_t m0 = bm + mt * 16 + lr;
            int n0 = bn + wn * 32 + nt * 8 + 2 * lc;
            symOut[m0 * (Nn * Ss) + n0]           = acc[mt][nt][0];
            symOut[m0 * (Nn * Ss) + n0 + 1]       = acc[mt][nt][1];
            symOut[(m0 + 8) * (Nn * Ss) + n0]     = acc[mt][nt][2];
            symOut[(m0 + 8) * (Nn * Ss) + n0 + 1] = acc[mt][nt][3];
        }
}

// ================== symmean[b,s] = mean_n sym[b,n,s] ==================
__global__ void mean_kernel(const float* __restrict__ symOut) {
    int i = blockIdx.x * blockDim.x + threadIdx.x;
    int b = i >> 7, s = i & 127;
    const float* p = symOut + (size_t)b * (Nn * Ss) + s;
    float sum = 0.f;
#pragma unroll
    for (int n = 0; n < Nn; n++) sum += p[n * Ss];
    g_symmean[i] = sum * 0.125f;
}

// ====== router: compensated-fp32 logits, split-k x4 + exact merge; argmax -> prog ======
// 4 tokens/block; 576 thr = 4 tok x 36 logits x 4 k-slices (160 elems each).
__global__ __launch_bounds__(576) void router_kernel(
    const float* __restrict__ RW, const float* __restrict__ rb, float* __restrict__ progf) {
    __shared__ float rin[4][644];
    __shared__ float ps[4][36][4], pc[4][36][4];
    __shared__ float lg[4][36];
    const int b0 = blockIdx.x * 4;
    const int tid = threadIdx.x;
    for (int i = tid; i < 4 * 640; i += 576) {
        int t = i / 640, k = i - t * 640;
        rin[t][k] = (k < Dm) ? g_z[(size_t)(b0 + t) * Dm + k]
                             : g_symmean[(size_t)(b0 + t) * Ss + (k - Dm)];
    }
    __syncthreads();
    {
        const int t  = tid / 144;
        const int r  = tid - t * 144;
        const int j  = r % 36;
        const int ks = r / 36;
        const int kbeg = ks * 160;
        const float* rw = RW + j;
        float s0 = 0.f, s1 = 0.f, c0 = 0.f, c1 = 0.f;
#pragma unroll 4
        for (int k = kbeg; k < kbeg + 160; k += 2) {
            {
                float x = rin[t][k];
                float w = __ldg(&rw[k * 36]);
                float p = __fmul_rn(x, w);
                float e = __fmaf_rn(x, w, -p);
                float S, er; two_sum(s0, p, S, er);
                s0 = S; c0 = __fadd_rn(c0, __fadd_rn(er, e));
            }
            {
                float x = rin[t][k + 1];
                float w = __ldg(&rw[(k + 1) * 36]);
                float p = __fmul_rn(x, w);
                float e = __fmaf_rn(x, w, -p);
                float S, er; two_sum(s1, p, S, er);
                s1 = S; c1 = __fadd_rn(c1, __fadd_rn(er, e));
            }
        }
        float S, er; two_sum(s0, s1, S, er);
        ps[t][j][ks] = S;
        pc[t][j][ks] = __fadd_rn(c0, __fadd_rn(c1, er));
    }
    __syncthreads();
    if (tid < 144) {
        int t = tid / 36, j = tid - t * 36;
        float S = ps[t][j][0], C = pc[t][j][0];
#pragma unroll
        for (int ks = 1; ks < 4; ks++) {
            float S2, er; two_sum(S, ps[t][j][ks], S2, er);
            S = S2;
            C = __fadd_rn(C, __fadd_rn(er, pc[t][j][ks]));
        }
        float S2, er; two_sum(S, rb[j], S2, er);
        lg[t][j] = __fadd_rn(S2, __fadd_rn(C, er));
    }
    __syncthreads();
    if (tid < 16) {
        int t = tid >> 2, h = tid & 3;
        const float* l = &lg[t][h * 9];
        float best = l[0]; int bi = 0;
#pragma unroll
        for (int j = 1; j < 9; j++)
            if (l[j] > best) { best = l[j]; bi = j; }   // first-max tie-break
        g_prog[(b0 + t) * HOPS + h] = bi;
        progf[(b0 + t) * HOPS + h] = (float)bi;
    }
}

// ======= schedule: group active tokens by (hop, expert); 64-row tiles =======
__global__ void schedule_kernel() {
    __shared__ int cnt[HOPS][Nn];
    __shared__ int cur[HOPS][Nn];
    const int tid = threadIdx.x;
    if (tid < HOPS * Nn) cnt[tid / Nn][tid % Nn] = 0;
    __syncthreads();
    for (int b = tid; b < Bsz; b += blockDim.x) {
        bool act = true;
        for (int t = 0; t < HOPS; t++) {
            int e = g_prog[b * HOPS + t];
            act = act && (e != Nn);
            if (act) atomicAdd(&cnt[t][e], 1);
        }
    }
    __syncthreads();
    if (tid < HOPS) {
        int t = tid, p = 0, nt = 0;
        for (int e = 0; e < Nn; e++) {
            cur[t][e] = p;
            int c = cnt[t][e], q = p;
            while (c > 0) {
                g_tileE[t][nt] = e; g_tileS[t][nt] = q;
                g_tileC[t][nt] = (c < TILEM) ? c : TILEM;
                q += TILEM; c -= TILEM; nt++;
            }
            p += cnt[t][e];
        }
        g_numTiles[t] = nt;
    }
    __syncthreads();
    for (int b = tid; b < Bsz; b += blockDim.x) {
        bool act = true;
        for (int t = 0; t < HOPS; t++) {
            int e = g_prog[b * HOPS + t];
            act = act && (e != Nn);
            if (act) { int p = atomicAdd(&cur[t][e], 1); g_order[t][p] = b; }
        }
    }
}

// == hop: dst[tok] = gelu(src[tok] @ ops_W[e] + ops_b[e]); gather via cp.async ==
// No inter-hop copies: active(h+1) ⊆ active(h).
__global__ __launch_bounds__(64) void hop_tc(
    int hop, int srcSel, const float* __restrict__ opsB) {
    if ((int)blockIdx.x >= g_numTiles[hop]) return;
    extern __shared__ uint32_t smem[];
    __shared__ int toks[TILEM];
    const float* src = (srcSel == 0) ? g_z : g_buf;
    float* dst = (srcSel == 0) ? g_buf : g_z;
    const int e     = g_tileE[hop][blockIdx.x];
    const int start = g_tileS[hop][blockIdx.x];
    const int cnt   = g_tileC[hop][blockIdx.x];
    const int bn    = blockIdx.y * 64;
    const int tid = threadIdx.x, lane = tid & 31, wn = tid >> 5;
    toks[tid] = (tid < cnt) ? g_order[hop][start + tid] : -1;
    __syncthreads();
    const uint32_t* WH = g_opsWH + (size_t)e * (Dm * Dm);
    const uint32_t* WL = g_opsWL + (size_t)e * (Dm * Dm);
    const int r = tid >> 3, colq = (tid & 7) * 4;
    int myTok[8];
#pragma unroll
    for (int i = 0; i < 8; i++) myTok[i] = toks[i * 8 + r];
    {
        uint32_t base = (uint32_t)__cvta_generic_to_shared(smem);
#pragma unroll
        for (int i = 0; i < 8; i++) {
            int row = i * 8 + r;
            int tk = myTok[i] < 0 ? 0 : myTok[i];
            cp_async16_z(base + (uint32_t)(row * A_ST + colq) * 4,
                         src + (size_t)tk * Dm + colq, myTok[i] >= 0 ? 16 : 0);
        }
    }
    stage_B64(smem, 0, WH, WL, (size_t)bn, Dm, tid);
    CP_COMMIT();
    float acc[4][4][4] = {};
    for (int k0 = 0; k0 < Dm; k0 += 32) {
        const int s = (k0 >> 5) & 1;
        CP_WAIT0();
        __syncthreads();
        if (k0 + 32 < Dm) {
            uint32_t base = (uint32_t)__cvta_generic_to_shared(smem + (s ^ 1) * 2304);
#pragma unroll
            for (int i = 0; i < 8; i++) {
                int row = i * 8 + r;
                int tk = myTok[i] < 0 ? 0 : myTok[i];
                cp_async16_z(base + (uint32_t)(row * A_ST + colq) * 4,
                             src + (size_t)tk * Dm + k0 + 32 + colq, myTok[i] >= 0 ? 16 : 0);
            }
            stage_B64(smem, s ^ 1, WH, WL, (size_t)(k0 + 32) * Dm + bn, Dm, tid);
        }
        CP_COMMIT();
        const float* As = reinterpret_cast<const float*>(smem + s * 2304);
        const uint32_t* Bh = smem + 4608 + s * 4608;
        const uint32_t* Bl = Bh + 2304;
        mma_k8f(As, Bh, Bl, wn, lane, 0, acc);
        mma_k8f(As, Bh, Bl, wn, lane, 8, acc);
        mma_k8f(As, Bh, Bl, wn, lane, 16, acc);
        mma_k8f(As, Bh, Bl, wn, lane, 24, acc);
        __syncthreads();
    }
    const int lr = lane >> 2, lc = lane & 3;
#pragma unroll
    for (int mt = 0; mt < 4; mt++) {
        int r0 = mt * 16 + lr;
        int tk0 = toks[r0], tk1 = toks[r0 + 8];
#pragma unroll
        for (int nt = 0; nt < 4; nt++) {
            int n0 = bn + wn * 32 + nt * 8 + 2 * lc;
            float b0 = opsB[e * Dm + n0], b1 = opsB[e * Dm + n0 + 1];
            if (tk0 >= 0) {
                dst[(size_t)tk0 * Dm + n0]     = gelu_tanh(acc[mt][nt][0] + b0);
                dst[(size_t)tk0 * Dm + n0 + 1] = gelu_tanh(acc[mt][nt][1] + b1);
            }
            if (tk1 >= 0) {
                dst[(size_t)tk1 * Dm + n0]     = gelu_tanh(acc[mt][nt][2] + b0);
                dst[(size_t)tk1 * Dm + n0 + 1] = gelu_tanh(acc[mt][nt][3] + b1);
            }
        }
    }
}

// ===== final gather: out[b] = buffer holding b's value after its last active hop =====
__global__ void gather_out(float* __restrict__ out) {
    int idx = blockIdx.x * blockDim.x + threadIdx.x;   // over Bsz*Dm/4 float4s
    int b = idx >> 7;
    int nact = 0;
#pragma unroll
    for (int t = 0; t < HOPS; t++) {
        if (g_prog[b * HOPS + t] == Nn) break;
        nact++;
    }
    const float* src = (nact & 1) ? g_buf : g_z;
    reinterpret_cast<float4*>(out)[idx] = reinterpret_cast<const float4*>(src)[idx];
}

// =========================== launch ===========================
extern "C" void kernel_launch(void* const* d_in, const int* in_sizes, int n_in,
                              void* d_out, int out_size) {
    const float* x        = (const float*)d_in[0];
    const float* W_in     = (const float*)d_in[1];
    const float* b_in     = (const float*)d_in[2];
    const float* ops_W    = (const float*)d_in[3];
    const float* ops_b    = (const float*)d_in[4];
    const float* sym_W    = (const float*)d_in[5];
    const float* router_W = (const float*)d_in[6];
    const float* router_b = (const float*)d_in[7];
    (void)in_sizes; (void)n_in; (void)out_size;

    float* out   = (float*)d_out;                 // [B, D]
    float* progf = out + Bsz * Dm;                // [B, HOPS] as float
    float* sym   = progf + Bsz * HOPS;            // [B, N, S]

    cudaFuncSetAttribute(gemm_z_tc,   cudaFuncAttributeMaxDynamicSharedMemorySize, SMEM_BYTES);
    cudaFuncSetAttribute(gemm_sym_tc, cudaFuncAttributeMaxDynamicSharedMemorySize, SMEM_BYTES);
    cudaFuncSetAttribute(hop_tc,      cudaFuncAttributeMaxDynamicSharedMemorySize, SMEM_BYTES);

    // pre-split weights into tf32 hi/lo
    split_sel<<<(INDIM * Dm / 4 + 255) / 256, 256>>>(W_in, 0, INDIM * Dm / 4);
    split_sel<<<(Nn * Dm * Ss / 4 + 255) / 256, 256>>>(sym_W, 1, Nn * Dm * Ss / 4);
    split_sel<<<(Nn * Dm * Dm / 4 + 255) / 256, 256>>>(ops_W, 2, Nn * Dm * Dm / 4);

    gemm_z_tc   <<<dim3(Bsz / TILEM, Dm / 64), 64, SMEM_BYTES>>>(x, b_in);
    gemm_sym_tc <<<dim3(Bsz / TILEM, (Nn * Ss) / 64), 64, SMEM_BYTES>>>(sym);
    mean_kernel <<<(Bsz * Ss) / 256, 256>>>(sym);
    router_kernel<<<Bsz / 4, 576>>>(router_W, router_b, progf);
    schedule_kernel<<<1, 512>>>();

    hop_tc<<<dim3(MAXT, Dm / 64), 64, SMEM_BYTES>>>(0, 0, ops_b);  // z   -> buf
    hop_tc<<<dim3(MAXT, Dm / 64), 64, SMEM_BYTES>>>(1, 1, ops_b);  // buf -> z
    hop_tc<<<dim3(MAXT, Dm / 64), 64, SMEM_BYTES>>>(2, 0, ops_b);  // z   -> buf
    hop_tc<<<dim3(MAXT, Dm / 64), 64, SMEM_BYTES>>>(3, 1, ops_b);  // buf -> z

    gather_out<<<(Bsz * Dm / 4) / 256, 256>>>(out);
}

// round 9
// speedup vs baseline: 1.2199x; 1.2129x over previous
#include <cuda_runtime.h>
#include <cuda_fp16.h>
#include <math.h>
#include <stdint.h>

// Problem constants (fixed by the reference)
#define Bsz   4096
#define INDIM 1024
#define Dm    512
#define Nn    8
#define Ss    128
#define HOPS  4
#define TILEM 64
#define MAXT  72      // max token tiles per hop: 4096/64 + 8

// packed-plane geometry (all K dims packed by pairs into half2 words)
#define A_ST2 20      // A smem stride (words): frag banks (20*lr+lc)%32 distinct
#define B_ST2 72      // B smem stride: banks (8*lc+lr) distinct
// dynamic smem (words):
//   A stage s: hi [64][20] @ s*2560, lo @ +1280
//   B stage s: hi [16][72] @ 5120+s*2304, lo @ +1152
#define SMEM_WORDS 9728
#define SMEM_BYTES (SMEM_WORDS * 4)   // 38912

// -------- device scratch (no allocations allowed) --------
__device__ float    g_z[Bsz * Dm];          // fp32 z (router input only)
__device__ float    g_symmean[Bsz * Ss];
__device__ int      g_prog[Bsz * HOPS];
__device__ int      g_order[HOPS][Bsz];
__device__ int      g_tileE[HOPS][MAXT];
__device__ int      g_tileS[HOPS][MAXT];
__device__ int      g_tileC[HOPS][MAXT];
__device__ int      g_numTiles[HOPS];
// packed fp16 hi/lo planes (words = half2)
__device__ uint32_t g_xH[Bsz * INDIM / 2],  g_xL[Bsz * INDIM / 2];
__device__ uint32_t g_zH[Bsz * Dm / 2],     g_zL[Bsz * Dm / 2];      // ping
__device__ uint32_t g_bufH[Bsz * Dm / 2],   g_bufL[Bsz * Dm / 2];    // pong
__device__ uint32_t g_WinH[(INDIM / 2) * Dm],  g_WinL[(INDIM / 2) * Dm];
__device__ uint32_t g_symWH[Nn * (Dm / 2) * Ss], g_symWL[Nn * (Dm / 2) * Ss];
__device__ uint32_t g_opsWH[Nn * (Dm / 2) * Dm], g_opsWL[Nn * (Dm / 2) * Dm];

__device__ __forceinline__ float gelu_tanh(float x) {
    float x3 = x * x * x;
    return 0.5f * x * (1.0f + tanhf(0.7978845608028654f * (x + 0.044715f * x3)));
}

// ---------------- fp16 hi/lo split helpers ----------------
__device__ __forceinline__ void splitH(float v, __half& h, __half& l) {
    h = __float2half_rn(v);
    l = __float2half_rn(__fsub_rn(v, __half2float(h)));
}
__device__ __forceinline__ uint32_t packH(__half a, __half b) {
    __half2 p = __halves2half2(a, b);
    return *reinterpret_cast<uint32_t*>(&p);
}
// exact TwoSum (router)
__device__ __forceinline__ void two_sum(float a, float b, float& s, float& e) {
    s = __fadd_rn(a, b);
    float bv = __fsub_rn(s, a);
    e = __fadd_rn(__fsub_rn(a, __fsub_rn(s, bv)), __fsub_rn(b, bv));
}

#define MMAF16(d, a, b)                                                       \
    asm("mma.sync.aligned.m16n8k16.row.col.f32.f16.f16.f32 "                  \
        "{%0,%1,%2,%3}, {%4,%5,%6,%7}, {%8,%9}, {%0,%1,%2,%3};"               \
        : "+f"(d[0]), "+f"(d[1]), "+f"(d[2]), "+f"(d[3])                      \
        : "r"(a[0]), "r"(a[1]), "r"(a[2]), "r"(a[3]), "r"(b[0]), "r"(b[1]))

// ---------------- cp.async helpers ----------------
__device__ __forceinline__ void cp_async16(uint32_t saddr, const void* g) {
    asm volatile("cp.async.cg.shared.global [%0], [%1], 16;" :: "r"(saddr), "l"(g));
}
__device__ __forceinline__ void cp_async16_z(uint32_t saddr, const void* g, int srcsz) {
    asm volatile("cp.async.cg.shared.global [%0], [%1], 16, %2;"
                 :: "r"(saddr), "l"(g), "r"(srcsz));
}
#define CP_COMMIT() asm volatile("cp.async.commit_group;")
#define CP_WAIT0()  asm volatile("cp.async.wait_group 0;" ::: "memory")

// Stage A slab: 64 rows x 16 words, hi+lo planes. 128 threads: r=tid>>1, plane=tid&1.
__device__ __forceinline__ void stage_A2(uint32_t* smem, int s,
                                         const uint32_t* __restrict__ GH,
                                         const uint32_t* __restrict__ GL,
                                         size_t row0, int ldw, int k2col, int tid) {
    const int r = tid >> 1, plane = tid & 1;
    const uint32_t* G = plane ? GL : GH;
    uint32_t base = (uint32_t)__cvta_generic_to_shared(smem + s * 2560 + plane * 1280);
#pragma unroll
    for (int c = 0; c < 4; c++) {
        int col = c * 4;
        cp_async16(base + (uint32_t)(r * A_ST2 + col) * 4,
                   G + (row0 + r) * ldw + k2col + col);
    }
}

// Stage A slab with token gather (hop). tok<0 rows zero-filled.
__device__ __forceinline__ void stage_A2g(uint32_t* smem, int s,
                                          const uint32_t* __restrict__ GH,
                                          const uint32_t* __restrict__ GL,
                                          int tok, int k2col, int tid) {
    const int r = tid >> 1, plane = tid & 1;
    const uint32_t* G = plane ? GL : GH;
    uint32_t base = (uint32_t)__cvta_generic_to_shared(smem + s * 2560 + plane * 1280);
    size_t row = (size_t)(tok < 0 ? 0 : tok);
    int sz = tok < 0 ? 0 : 16;
#pragma unroll
    for (int c = 0; c < 4; c++) {
        int col = c * 4;
        cp_async16_z(base + (uint32_t)(r * A_ST2 + col) * 4,
                     G + row * (Dm / 2) + k2col + col, sz);
    }
    (void)r;
}

// Stage B slab: 16 k2-rows x 64 n words, hi+lo. 128 threads.
__device__ __forceinline__ void stage_B2(uint32_t* smem, int s,
                                         const uint32_t* __restrict__ GH,
                                         const uint32_t* __restrict__ GL,
                                         size_t gbase, int ldw, int tid) {
    uint32_t base_h = (uint32_t)__cvta_generic_to_shared(smem + 5120 + s * 2304);
    uint32_t base_l = base_h + 1152 * 4;
#pragma unroll
    for (int p = 0; p < 2; p++) {
        int q = tid + p * 128;
        int row = q >> 4, col = (q & 15) * 4;
        uint32_t soff = (uint32_t)(row * B_ST2 + col) * 4;
        size_t goff = gbase + (size_t)row * ldw + col;
        cp_async16(base_h + soff, GH + goff);
        cp_async16(base_l + soff, GL + goff);
    }
}

// One k16 step: warp (wm,wn) computes 32x32 (2 m-tiles x 4 n-tiles), 3xFP16.
__device__ __forceinline__ void mma_k16(
    const uint32_t* __restrict__ smem, int s, int wm, int wn, int lane, int k2off,
    float acc[2][4][4]) {
    const uint32_t* AhS = smem + s * 2560;
    const uint32_t* AlS = AhS + 1280;
    const uint32_t* BhS = smem + 5120 + s * 2304;
    const uint32_t* BlS = BhS + 1152;
    const int lr = lane >> 2, lc = lane & 3;
    uint32_t ah[2][4], al[2][4];
#pragma unroll
    for (int mt = 0; mt < 2; mt++) {
        int m = wm * 32 + mt * 16 + lr;
        ah[mt][0] = AhS[m * A_ST2 + k2off + lc];
        ah[mt][1] = AhS[(m + 8) * A_ST2 + k2off + lc];
        ah[mt][2] = AhS[m * A_ST2 + k2off + 4 + lc];
        ah[mt][3] = AhS[(m + 8) * A_ST2 + k2off + 4 + lc];
        al[mt][0] = AlS[m * A_ST2 + k2off + lc];
        al[mt][1] = AlS[(m + 8) * A_ST2 + k2off + lc];
        al[mt][2] = AlS[m * A_ST2 + k2off + 4 + lc];
        al[mt][3] = AlS[(m + 8) * A_ST2 + k2off + 4 + lc];
    }
#pragma unroll
    for (int nt = 0; nt < 4; nt++) {
        int n = wn * 32 + nt * 8 + lr;
        uint32_t bh[2], bl[2];
        bh[0] = BhS[(k2off + lc) * B_ST2 + n];
        bh[1] = BhS[(k2off + 4 + lc) * B_ST2 + n];
        bl[0] = BlS[(k2off + lc) * B_ST2 + n];
        bl[1] = BlS[(k2off + 4 + lc) * B_ST2 + n];
#pragma unroll
        for (int mt = 0; mt < 2; mt++) {
            MMAF16(acc[mt][nt], ah[mt], bl);
            MMAF16(acc[mt][nt], al[mt], bh);
            MMAF16(acc[mt][nt], ah[mt], bh);
        }
    }
}

// ============ pre-split kernels ============
// x: pairs contiguous along IN_DIM
__global__ void split_x(const float* __restrict__ x) {
    int i = blockIdx.x * blockDim.x + threadIdx.x;   // over Bsz*INDIM/2
    float2 v = reinterpret_cast<const float2*>(x)[i];
    __half h0, l0, h1, l1;
    splitH(v.x, h0, l0); splitH(v.y, h1, l1);
    g_xH[i] = packH(h0, h1);
    g_xL[i] = packH(l0, l1);
}
// weights: pair elements (2r2)*C+c, (2r2+1)*C+c  (works for Win/sym/ops flattened)
__global__ void split_wk(const float* __restrict__ src, int sel, int nw, int C) {
    int i = blockIdx.x * blockDim.x + threadIdx.x;
    if (i >= nw) return;
    uint32_t* WH = (sel == 0) ? g_WinH : (sel == 1) ? g_symWH : g_opsWH;
    uint32_t* WL = (sel == 0) ? g_WinL : (sel == 1) ? g_symWL : g_opsWL;
    int r2 = i / C, c = i - r2 * C;
    float f0 = src[(size_t)(2 * r2) * C + c];
    float f1 = src[(size_t)(2 * r2 + 1) * C + c];
    __half h0, l0, h1, l1;
    splitH(f0, h0, l0); splitH(f1, h1, l1);
    WH[i] = packH(h0, h1);
    WL[i] = packH(l0, l1);
}

// ============ GEMM 1: z = x @ W_in + b_in (block 64x64, 4 warps 32x32) ============
// writes fp32 z (router) + packed zH/zL planes (sym + hop0 A operand)
__global__ __launch_bounds__(128) void gemm_z_tc(const float* __restrict__ bias) {
    extern __shared__ uint32_t smem[];
    const int tid = threadIdx.x, lane = tid & 31, warp = tid >> 5;
    const int wm = warp & 1, wn = warp >> 1;
    const size_t bm = blockIdx.x * TILEM;
    const int bn = blockIdx.y * 64;
    float acc[2][4][4] = {};
    stage_A2(smem, 0, g_xH, g_xL, bm, INDIM / 2, 0, tid);
    stage_B2(smem, 0, g_WinH, g_WinL, (size_t)bn, Dm, tid);
    CP_COMMIT();
    for (int k0 = 0; k0 < INDIM; k0 += 32) {
        const int s = (k0 >> 5) & 1;
        CP_WAIT0();
        __syncthreads();
        if (k0 + 32 < INDIM) {
            stage_A2(smem, s ^ 1, g_xH, g_xL, bm, INDIM / 2, (k0 + 32) / 2, tid);
            stage_B2(smem, s ^ 1, g_WinH, g_WinL, (size_t)((k0 + 32) / 2) * Dm + bn, Dm, tid);
        }
        CP_COMMIT();
        mma_k16(smem, s, wm, wn, lane, 0, acc);
        mma_k16(smem, s, wm, wn, lane, 8, acc);
        __syncthreads();
    }
    const int lr = lane >> 2, lc = lane & 3;
#pragma unroll
    for (int mt = 0; mt < 2; mt++)
#pragma unroll
        for (int nt = 0; nt < 4; nt++) {
            size_t m0 = bm + wm * 32 + mt * 16 + lr;
            int n0 = bn + wn * 32 + nt * 8 + 2 * lc;
            float b0 = bias[n0], b1 = bias[n0 + 1];
            float v00 = acc[mt][nt][0] + b0, v01 = acc[mt][nt][1] + b1;
            float v10 = acc[mt][nt][2] + b0, v11 = acc[mt][nt][3] + b1;
            g_z[m0 * Dm + n0] = v00;           g_z[m0 * Dm + n0 + 1] = v01;
            g_z[(m0 + 8) * Dm + n0] = v10;     g_z[(m0 + 8) * Dm + n0 + 1] = v11;
            __half h0, l0, h1, l1;
            splitH(v00, h0, l0); splitH(v01, h1, l1);
            g_zH[m0 * (Dm / 2) + n0 / 2] = packH(h0, h1);
            g_zL[m0 * (Dm / 2) + n0 / 2] = packH(l0, l1);
            splitH(v10, h0, l0); splitH(v11, h1, l1);
            g_zH[(m0 + 8) * (Dm / 2) + n0 / 2] = packH(h0, h1);
            g_zL[(m0 + 8) * (Dm / 2) + n0 / 2] = packH(l0, l1);
        }
}

// ======= GEMM 2: sym[b, n*128+s] = sum_d z[b,d]*sym_W[n,d,s] (fp32 out) =======
__global__ __launch_bounds__(128) void gemm_sym_tc(float* __restrict__ symOut) {
    extern __shared__ uint32_t smem[];
    const int tid = threadIdx.x, lane = tid & 31, warp = tid >> 5;
    const int wm = warp & 1, wn = warp >> 1;
    const size_t bm = blockIdx.x * TILEM;
    const int bn = blockIdx.y * 64;
    const size_t boff = (size_t)(bn >> 7) * ((Dm / 2) * Ss) + (bn & 127);
    float acc[2][4][4] = {};
    stage_A2(smem, 0, g_zH, g_zL, bm, Dm / 2, 0, tid);
    stage_B2(smem, 0, g_symWH, g_symWL, boff, Ss, tid);
    CP_COMMIT();
    for (int k0 = 0; k0 < Dm; k0 += 32) {
        const int s = (k0 >> 5) & 1;
        CP_WAIT0();
        __syncthreads();
        if (k0 + 32 < Dm) {
            stage_A2(smem, s ^ 1, g_zH, g_zL, bm, Dm / 2, (k0 + 32) / 2, tid);
            stage_B2(smem, s ^ 1, g_symWH, g_symWL,
                     boff + (size_t)((k0 + 32) / 2) * Ss, Ss, tid);
        }
        CP_COMMIT();
        mma_k16(smem, s, wm, wn, lane, 0, acc);
        mma_k16(smem, s, wm, wn, lane, 8, acc);
        __syncthreads();
    }
    const int lr = lane >> 2, lc = lane & 3;
#pragma unroll
    for (int mt = 0; mt < 2; mt++)
#pragma unroll
        for (int nt = 0; nt < 4; nt++) {
            size_t m0 = bm + wm * 32 + mt * 16 + lr;
            int n0 = bn + wn * 32 + nt * 8 + 2 * lc;
            symOut[m0 * (Nn * Ss) + n0]           = acc[mt][nt][0];
            symOut[m0 * (Nn * Ss) + n0 + 1]       = acc[mt][nt][1];
            symOut[(m0 + 8) * (Nn * Ss) + n0]     = acc[mt][nt][2];
            symOut[(m0 + 8) * (Nn * Ss) + n0 + 1] = acc[mt][nt][3];
        }
}

// ================== symmean[b,s] = mean_n sym[b,n,s] ==================
__global__ void mean_kernel(const float* __restrict__ symOut) {
    int i = blockIdx.x * blockDim.x + threadIdx.x;
    int b = i >> 7, s = i & 127;
    const float* p = symOut + (size_t)b * (Nn * Ss) + s;
    float sum = 0.f;
#pragma unroll
    for (int n = 0; n < Nn; n++) sum += p[n * Ss];
    g_symmean[i] = sum * 0.125f;
}

// ====== router: compensated-fp32 split-k x4 + exact merge; argmax -> prog ======
__global__ __launch_bounds__(576) void router_kernel(
    const float* __restrict__ RW, const float* __restrict__ rb, float* __restrict__ progf) {
    __shared__ float rin[4][644];
    __shared__ float ps[4][36][4], pc[4][36][4];
    __shared__ float lg[4][36];
    const int b0 = blockIdx.x * 4;
    const int tid = threadIdx.x;
    for (int i = tid; i < 4 * 640; i += 576) {
        int t = i / 640, k = i - t * 640;
        rin[t][k] = (k < Dm) ? g_z[(size_t)(b0 + t) * Dm + k]
                             : g_symmean[(size_t)(b0 + t) * Ss + (k - Dm)];
    }
    __syncthreads();
    {
        const int t  = tid / 144;
        const int r  = tid - t * 144;
        const int j  = r % 36;
        const int ks = r / 36;
        const int kbeg = ks * 160;
        const float* rw = RW + j;
        float s0 = 0.f, s1 = 0.f, c0 = 0.f, c1 = 0.f;
#pragma unroll 4
        for (int k = kbeg; k < kbeg + 160; k += 2) {
            {
                float x = rin[t][k];
                float w = __ldg(&rw[k * 36]);
                float p = __fmul_rn(x, w);
                float e = __fmaf_rn(x, w, -p);
                float S, er; two_sum(s0, p, S, er);
                s0 = S; c0 = __fadd_rn(c0, __fadd_rn(er, e));
            }
            {
                float x = rin[t][k + 1];
                float w = __ldg(&rw[(k + 1) * 36]);
                float p = __fmul_rn(x, w);
                float e = __fmaf_rn(x, w, -p);
                float S, er; two_sum(s1, p, S, er);
                s1 = S; c1 = __fadd_rn(c1, __fadd_rn(er, e));
            }
        }
        float S, er; two_sum(s0, s1, S, er);
        ps[t][j][ks] = S;
        pc[t][j][ks] = __fadd_rn(c0, __fadd_rn(c1, er));
    }
    __syncthreads();
    if (tid < 144) {
        int t = tid / 36, j = tid - t * 36;
        float S = ps[t][j][0], C = pc[t][j][0];
#pragma unroll
        for (int ks = 1; ks < 4; ks++) {
            float S2, er; two_sum(S, ps[t][j][ks], S2, er);
            S = S2;
            C = __fadd_rn(C, __fadd_rn(er, pc[t][j][ks]));
        }
        float S2, er; two_sum(S, rb[j], S2, er);
        lg[t][j] = __fadd_rn(S2, __fadd_rn(C, er));
    }
    __syncthreads();
    if (tid < 16) {
        int t = tid >> 2, h = tid & 3;
        const float* l = &lg[t][h * 9];
        float best = l[0]; int bi = 0;
#pragma unroll
        for (int j = 1; j < 9; j++)
            if (l[j] > best) { best = l[j]; bi = j; }   // first-max tie-break
        g_prog[(b0 + t) * HOPS + h] = bi;
        progf[(b0 + t) * HOPS + h] = (float)bi;
    }
}

// ======= schedule: group active tokens by (hop, expert); 64-row tiles =======
__global__ void schedule_kernel() {
    __shared__ int cnt[HOPS][Nn];
    __shared__ int cur[HOPS][Nn];
    const int tid = threadIdx.x;
    if (tid < HOPS * Nn) cnt[tid / Nn][tid % Nn] = 0;
    __syncthreads();
    for (int b = tid; b < Bsz; b += blockDim.x) {
        bool act = true;
        for (int t = 0; t < HOPS; t++) {
            int e = g_prog[b * HOPS + t];
            act = act && (e != Nn);
            if (act) atomicAdd(&cnt[t][e], 1);
        }
    }
    __syncthreads();
    if (tid < HOPS) {
        int t = tid, p = 0, nt = 0;
        for (int e = 0; e < Nn; e++) {
            cur[t][e] = p;
            int c = cnt[t][e], q = p;
            while (c > 0) {
                g_tileE[t][nt] = e; g_tileS[t][nt] = q;
                g_tileC[t][nt] = (c < TILEM) ? c : TILEM;
                q += TILEM; c -= TILEM; nt++;
            }
            p += cnt[t][e];
        }
        g_numTiles[t] = nt;
    }
    __syncthreads();
    for (int b = tid; b < Bsz; b += blockDim.x) {
        bool act = true;
        for (int t = 0; t < HOPS; t++) {
            int e = g_prog[b * HOPS + t];
            act = act && (e != Nn);
            if (act) { int p = atomicAdd(&cur[t][e], 1); g_order[t][p] = b; }
        }
    }
}

// == hop: dst planes[tok] = split(gelu(src[tok] @ ops_W[e] + ops_b[e])) ==
// No inter-hop copies: active(h+1) ⊆ active(h). Outputs stored only as hi/lo planes.
__global__ __launch_bounds__(128) void hop_tc(
    int hop, int srcSel, const float* __restrict__ opsB) {
    if ((int)blockIdx.x >= g_numTiles[hop]) return;
    extern __shared__ uint32_t smem[];
    __shared__ int toks[TILEM];
    const uint32_t* srcH = (srcSel == 0) ? g_zH : g_bufH;
    const uint32_t* srcL = (srcSel == 0) ? g_zL : g_bufL;
    uint32_t* dstH = (srcSel == 0) ? g_bufH : g_zH;
    uint32_t* dstL = (srcSel == 0) ? g_bufL : g_zL;
    const int e     = g_tileE[hop][blockIdx.x];
    const int start = g_tileS[hop][blockIdx.x];
    const int cnt   = g_tileC[hop][blockIdx.x];
    const int bn    = blockIdx.y * 64;
    const int tid = threadIdx.x, lane = tid & 31, warp = tid >> 5;
    const int wm = warp & 1, wn = warp >> 1;
    if (tid < TILEM) toks[tid] = (tid < cnt) ? g_order[hop][start + tid] : -1;
    __syncthreads();
    const uint32_t* WH = g_opsWH + (size_t)e * ((Dm / 2) * Dm);
    const uint32_t* WL = g_opsWL + (size_t)e * ((Dm / 2) * Dm);
    const int myTok = toks[tid >> 1];
    stage_A2g(smem, 0, srcH, srcL, myTok, 0, tid);
    stage_B2(smem, 0, WH, WL, (size_t)bn, Dm, tid);
    CP_COMMIT();
    float acc[2][4][4] = {};
    for (int k0 = 0; k0 < Dm; k0 += 32) {
        const int s = (k0 >> 5) & 1;
        CP_WAIT0();
        __syncthreads();
        if (k0 + 32 < Dm) {
            stage_A2g(smem, s ^ 1, srcH, srcL, myTok, (k0 + 32) / 2, tid);
            stage_B2(smem, s ^ 1, WH, WL, (size_t)((k0 + 32) / 2) * Dm + bn, Dm, tid);
        }
        CP_COMMIT();
        mma_k16(smem, s, wm, wn, lane, 0, acc);
        mma_k16(smem, s, wm, wn, lane, 8, acc);
        __syncthreads();
    }
    const int lr = lane >> 2, lc = lane & 3;
#pragma unroll
    for (int mt = 0; mt < 2; mt++) {
        int r0 = wm * 32 + mt * 16 + lr;
        int tk0 = toks[r0], tk1 = toks[r0 + 8];
#pragma unroll
        for (int nt = 0; nt < 4; nt++) {
            int n0 = bn + wn * 32 + nt * 8 + 2 * lc;
            float b0 = opsB[e * Dm + n0], b1 = opsB[e * Dm + n0 + 1];
            if (tk0 >= 0) {
                float v0 = gelu_tanh(acc[mt][nt][0] + b0);
                float v1 = gelu_tanh(acc[mt][nt][1] + b1);
                __half h0, l0, h1, l1;
                splitH(v0, h0, l0); splitH(v1, h1, l1);
                dstH[(size_t)tk0 * (Dm / 2) + n0 / 2] = packH(h0, h1);
                dstL[(size_t)tk0 * (Dm / 2) + n0 / 2] = packH(l0, l1);
            }
            if (tk1 >= 0) {
                float v0 = gelu_tanh(acc[mt][nt][2] + b0);
                float v1 = gelu_tanh(acc[mt][nt][3] + b1);
                __half h0, l0, h1, l1;
                splitH(v0, h0, l0); splitH(v1, h1, l1);
                dstH[(size_t)tk1 * (Dm / 2) + n0 / 2] = packH(h0, h1);
                dstL[(size_t)tk1 * (Dm / 2) + n0 / 2] = packH(l0, l1);
            }
        }
    }
}

// ===== final gather: reconstruct fp32 out from the parity-selected plane pair =====
__global__ void gather_out(float* __restrict__ out) {
    int idx = blockIdx.x * blockDim.x + threadIdx.x;   // over Bsz*Dm/2 words
    int b = idx >> 8;
    int nact = 0;
#pragma unroll
    for (int t = 0; t < HOPS; t++) {
        if (g_prog[b * HOPS + t] == Nn) break;
        nact++;
    }
    const uint32_t* sH = (nact & 1) ? g_bufH : g_zH;
    const uint32_t* sL = (nact & 1) ? g_bufL : g_zL;
    uint32_t wh = sH[idx], wl = sL[idx];
    __half2 h = *reinterpret_cast<__half2*>(&wh);
    __half2 l = *reinterpret_cast<__half2*>(&wl);
    float2 o;
    o.x = __fadd_rn(__half2float(__low2half(h)),  __half2float(__low2half(l)));
    o.y = __fadd_rn(__half2float(__high2half(h)), __half2float(__high2half(l)));
    reinterpret_cast<float2*>(out)[idx] = o;
}

// =========================== launch ===========================
extern "C" void kernel_launch(void* const* d_in, const int* in_sizes, int n_in,
                              void* d_out, int out_size) {
    const float* x        = (const float*)d_in[0];
    const float* W_in     = (const float*)d_in[1];
    const float* b_in     = (const float*)d_in[2];
    const float* ops_W    = (const float*)d_in[3];
    const float* ops_b    = (const float*)d_in[4];
    const float* sym_W    = (const float*)d_in[5];
    const float* router_W = (const float*)d_in[6];
    const float* router_b = (const float*)d_in[7];
    (void)W_in; (void)in_sizes; (void)n_in; (void)out_size;

    float* out   = (float*)d_out;                 // [B, D]
    float* progf = out + Bsz * Dm;                // [B, HOPS] as float
    float* sym   = progf + Bsz * HOPS;            // [B, N, S]

    cudaFuncSetAttribute(gemm_z_tc,   cudaFuncAttributeMaxDynamicSharedMemorySize, SMEM_BYTES);
    cudaFuncSetAttribute(gemm_sym_tc, cudaFuncAttributeMaxDynamicSharedMemorySize, SMEM_BYTES);
    cudaFuncSetAttribute(hop_tc,      cudaFuncAttributeMaxDynamicSharedMemorySize, SMEM_BYTES);

    // pre-split to packed fp16 hi/lo planes
    split_x <<<(Bsz * INDIM / 2) / 256, 256>>>(x);
    split_wk<<<((INDIM / 2) * Dm + 255) / 256, 256>>>(W_in, 0, (INDIM / 2) * Dm, Dm);
    split_wk<<<(Nn * (Dm / 2) * Ss + 255) / 256, 256>>>(sym_W, 1, Nn * (Dm / 2) * Ss, Ss);
    split_wk<<<(Nn * (Dm / 2) * Dm + 255) / 256, 256>>>(ops_W, 2, Nn * (Dm / 2) * Dm, Dm);

    gemm_z_tc   <<<dim3(Bsz / TILEM, Dm / 64), 128, SMEM_BYTES>>>(b_in);
    gemm_sym_tc <<<dim3(Bsz / TILEM, (Nn * Ss) / 64), 128, SMEM_BYTES>>>(sym);
    mean_kernel <<<(Bsz * Ss) / 256, 256>>>(sym);
    router_kernel<<<Bsz / 4, 576>>>(router_W, router_b, progf);
    schedule_kernel<<<1, 512>>>();

    hop_tc<<<dim3(MAXT, Dm / 64), 128, SMEM_BYTES>>>(0, 0, ops_b);  // z   -> buf
    hop_tc<<<dim3(MAXT, Dm / 64), 128, SMEM_BYTES>>>(1, 1, ops_b);  // buf -> z
    hop_tc<<<dim3(MAXT, Dm / 64), 128, SMEM_BYTES>>>(2, 0, ops_b);  // z   -> buf
    hop_tc<<<dim3(MAXT, Dm / 64), 128, SMEM_BYTES>>>(3, 1, ops_b);  // buf -> z

    gather_out<<<(Bsz * Dm / 2) / 256, 256>>>(out);
}

// round 13
// speedup vs baseline: 1.2337x; 1.0114x over previous
#include <cuda_runtime.h>
#include <cuda_fp16.h>
#include <math.h>
#include <stdint.h>

// Problem constants (fixed by the reference)
#define Bsz   4096
#define INDIM 1024
#define Dm    512
#define Nn    8
#define Ss    128
#define HOPS  4
#define TILEM 64
#define MAXT  72      // max token tiles per hop: 4096/64 + 8

// packed-plane geometry (all K dims packed by pairs into half2 words)
#define A_ST2 20      // A smem stride (words): frag banks (20*lr+lc)%32 distinct
#define B_ST2 72      // B smem stride: banks (8*lc+lr) distinct
// dynamic smem (words):
//   A stage s: hi [64][20] @ s*2560, lo @ +1280
//   B stage s: hi [16][72] @ 5120+s*2304, lo @ +1152
#define SMEM_WORDS 9728
#define SMEM_BYTES (SMEM_WORDS * 4)   // 38912

// split_all ranges (in word/items)
#define NX    (Bsz * INDIM / 2)        // 2097152
#define NWIN  ((INDIM / 2) * Dm)       // 262144
#define NSYM  (Nn * (Dm / 2) * Ss)     // 262144
#define NOPS  (Nn * (Dm / 2) * Dm)     // 1048576
#define NALL  (NX + NWIN + NSYM + NOPS)

// -------- device scratch (no allocations allowed) --------
__device__ float    g_z[Bsz * Dm];          // fp32 z (router input only)
__device__ float    g_symmean[Bsz * Ss];
__device__ int      g_prog[Bsz * HOPS];
__device__ int      g_order[HOPS][Bsz];
__device__ int      g_tileE[HOPS][MAXT];
__device__ int      g_tileS[HOPS][MAXT];
__device__ int      g_tileC[HOPS][MAXT];
__device__ int      g_numTiles[HOPS];
// packed fp16 hi/lo planes (word = half2)
__device__ uint32_t g_xH[Bsz * INDIM / 2],  g_xL[Bsz * INDIM / 2];
__device__ uint32_t g_zH[Bsz * Dm / 2],     g_zL[Bsz * Dm / 2];      // ping
__device__ uint32_t g_bufH[Bsz * Dm / 2],   g_bufL[Bsz * Dm / 2];    // pong
__device__ uint32_t g_WinH[(INDIM / 2) * Dm],  g_WinL[(INDIM / 2) * Dm];
__device__ uint32_t g_symWH[Nn * (Dm / 2) * Ss], g_symWL[Nn * (Dm / 2) * Ss];
__device__ uint32_t g_opsWH[Nn * (Dm / 2) * Dm], g_opsWL[Nn * (Dm / 2) * Dm];

__device__ __forceinline__ float gelu_tanh(float x) {
    float x3 = x * x * x;
    return 0.5f * x * (1.0f + tanhf(0.7978845608028654f * (x + 0.044715f * x3)));
}

// ---------------- fp16 hi/lo split helpers ----------------
__device__ __forceinline__ void splitH(float v, __half& h, __half& l) {
    h = __float2half_rn(v);
    l = __float2half_rn(__fsub_rn(v, __half2float(h)));
}
__device__ __forceinline__ uint32_t packH(__half a, __half b) {
    __half2 p = __halves2half2(a, b);
    return *reinterpret_cast<uint32_t*>(&p);
}
// exact TwoSum (router)
__device__ __forceinline__ void two_sum(float a, float b, float& s, float& e) {
    s = __fadd_rn(a, b);
    float bv = __fsub_rn(s, a);
    e = __fadd_rn(__fsub_rn(a, __fsub_rn(s, bv)), __fsub_rn(b, bv));
}

#define MMAF16(d, a, b)                                                       \
    asm("mma.sync.aligned.m16n8k16.row.col.f32.f16.f16.f32 "                  \
        "{%0,%1,%2,%3}, {%4,%5,%6,%7}, {%8,%9}, {%0,%1,%2,%3};"               \
        : "+f"(d[0]), "+f"(d[1]), "+f"(d[2]), "+f"(d[3])                      \
        : "r"(a[0]), "r"(a[1]), "r"(a[2]), "r"(a[3]), "r"(b[0]), "r"(b[1]))

// ---------------- cp.async helpers ----------------
__device__ __forceinline__ void cp_async16(uint32_t saddr, const void* g) {
    asm volatile("cp.async.cg.shared.global [%0], [%1], 16;" :: "r"(saddr), "l"(g));
}
__device__ __forceinline__ void cp_async16_z(uint32_t saddr, const void* g, int srcsz) {
    asm volatile("cp.async.cg.shared.global [%0], [%1], 16, %2;"
                 :: "r"(saddr), "l"(g), "r"(srcsz));
}
#define CP_COMMIT() asm volatile("cp.async.commit_group;")
#define CP_WAIT0()  asm volatile("cp.async.wait_group 0;" ::: "memory")

// Stage A slab: 64 rows x 16 words, hi+lo planes. 128 threads: r=tid>>1, plane=tid&1.
__device__ __forceinline__ void stage_A2(uint32_t* smem, int s,
                                         const uint32_t* __restrict__ GH,
                                         const uint32_t* __restrict__ GL,
                                         size_t row0, int ldw, int k2col, int tid) {
    const int r = tid >> 1, plane = tid & 1;
    const uint32_t* G = plane ? GL : GH;
    uint32_t base = (uint32_t)__cvta_generic_to_shared(smem + s * 2560 + plane * 1280);
#pragma unroll
    for (int c = 0; c < 4; c++) {
        int col = c * 4;
        cp_async16(base + (uint32_t)(r * A_ST2 + col) * 4,
                   G + (row0 + r) * ldw + k2col + col);
    }
}

// Stage A slab with token gather (hop). tok<0 rows zero-filled.
__device__ __forceinline__ void stage_A2g(uint32_t* smem, int s,
                                          const uint32_t* __restrict__ GH,
                                          const uint32_t* __restrict__ GL,
                                          int tok, int k2col, int tid) {
    const int r = tid >> 1, plane = tid & 1;
    const uint32_t* G = plane ? GL : GH;
    uint32_t base = (uint32_t)__cvta_generic_to_shared(smem + s * 2560 + plane * 1280);
    size_t row = (size_t)(tok < 0 ? 0 : tok);
    int sz = tok < 0 ? 0 : 16;
#pragma unroll
    for (int c = 0; c < 4; c++) {
        int col = c * 4;
        cp_async16_z(base + (uint32_t)(r * A_ST2 + col) * 4,
                     G + row * (Dm / 2) + k2col + col, sz);
    }
    (void)r;
}

// Stage B slab: 16 k2-rows x 64 n words, hi+lo. 128 threads.
__device__ __forceinline__ void stage_B2(uint32_t* smem, int s,
                                         const uint32_t* __restrict__ GH,
                                         const uint32_t* __restrict__ GL,
                                         size_t gbase, int ldw, int tid) {
    uint32_t base_h = (uint32_t)__cvta_generic_to_shared(smem + 5120 + s * 2304);
    uint32_t base_l = base_h + 1152 * 4;
#pragma unroll
    for (int p = 0; p < 2; p++) {
        int q = tid + p * 128;
        int row = q >> 4, col = (q & 15) * 4;
        uint32_t soff = (uint32_t)(row * B_ST2 + col) * 4;
        size_t goff = gbase + (size_t)row * ldw + col;
        cp_async16(base_h + soff, GH + goff);
        cp_async16(base_l + soff, GL + goff);
    }
}

// One k16 step: warp (wm,wn) computes 32x32 (2 m-tiles x 4 n-tiles), 3xFP16.
__device__ __forceinline__ void mma_k16(
    const uint32_t* __restrict__ smem, int s, int wm, int wn, int lane, int k2off,
    float acc[2][4][4]) {
    const uint32_t* AhS = smem + s * 2560;
    const uint32_t* AlS = AhS + 1280;
    const uint32_t* BhS = smem + 5120 + s * 2304;
    const uint32_t* BlS = BhS + 1152;
    const int lr = lane >> 2, lc = lane & 3;
    uint32_t ah[2][4], al[2][4];
#pragma unroll
    for (int mt = 0; mt < 2; mt++) {
        int m = wm * 32 + mt * 16 + lr;
        ah[mt][0] = AhS[m * A_ST2 + k2off + lc];
        ah[mt][1] = AhS[(m + 8) * A_ST2 + k2off + lc];
        ah[mt][2] = AhS[m * A_ST2 + k2off + 4 + lc];
        ah[mt][3] = AhS[(m + 8) * A_ST2 + k2off + 4 + lc];
        al[mt][0] = AlS[m * A_ST2 + k2off + lc];
        al[mt][1] = AlS[(m + 8) * A_ST2 + k2off + lc];
        al[mt][2] = AlS[m * A_ST2 + k2off + 4 + lc];
        al[mt][3] = AlS[(m + 8) * A_ST2 + k2off + 4 + lc];
    }
#pragma unroll
    for (int nt = 0; nt < 4; nt++) {
        int n = wn * 32 + nt * 8 + lr;
        uint32_t bh[2], bl[2];
        bh[0] = BhS[(k2off + lc) * B_ST2 + n];
        bh[1] = BhS[(k2off + 4 + lc) * B_ST2 + n];
        bl[0] = BlS[(k2off + lc) * B_ST2 + n];
        bl[1] = BlS[(k2off + 4 + lc) * B_ST2 + n];
#pragma unroll
        for (int mt = 0; mt < 2; mt++) {
            MMAF16(acc[mt][nt], ah[mt], bl);
            MMAF16(acc[mt][nt], al[mt], bh);
            MMAF16(acc[mt][nt], ah[mt], bh);
        }
    }
}

// ============ zero g_symmean (mean is accumulated by gemm_sym epilogue) ============
__global__ void zero_mean() {
    int i = blockIdx.x * blockDim.x + threadIdx.x;   // over Bsz*Ss/4
    reinterpret_cast<float4*>(g_symmean)[i] = make_float4(0.f, 0.f, 0.f, 0.f);
}

// ============ fused pre-split (x + all weights, one launch) ============
__global__ void split_all(const float* __restrict__ x, const float* __restrict__ Win,
                          const float* __restrict__ symW, const float* __restrict__ opsW) {
    int i = blockIdx.x * blockDim.x + threadIdx.x;
    __half h0, l0, h1, l1;
    if (i < NX) {
        float2 v = reinterpret_cast<const float2*>(x)[i];
        splitH(v.x, h0, l0); splitH(v.y, h1, l1);
        g_xH[i] = packH(h0, h1);
        g_xL[i] = packH(l0, l1);
    } else if (i < NX + NWIN) {
        int j = i - NX;
        int r2 = j / Dm, c = j - r2 * Dm;
        float f0 = Win[(size_t)(2 * r2) * Dm + c];
        float f1 = Win[(size_t)(2 * r2 + 1) * Dm + c];
        splitH(f0, h0, l0); splitH(f1, h1, l1);
        g_WinH[j] = packH(h0, h1);
        g_WinL[j] = packH(l0, l1);
    } else if (i < NX + NWIN + NSYM) {
        int j = i - NX - NWIN;
        int r2 = j / Ss, c = j - r2 * Ss;
        float f0 = symW[(size_t)(2 * r2) * Ss + c];
        float f1 = symW[(size_t)(2 * r2 + 1) * Ss + c];
        splitH(f0, h0, l0); splitH(f1, h1, l1);
        g_symWH[j] = packH(h0, h1);
        g_symWL[j] = packH(l0, l1);
    } else {
        int j = i - NX - NWIN - NSYM;
        int r2 = j / Dm, c = j - r2 * Dm;
        float f0 = opsW[(size_t)(2 * r2) * Dm + c];
        float f1 = opsW[(size_t)(2 * r2 + 1) * Dm + c];
        splitH(f0, h0, l0); splitH(f1, h1, l1);
        g_opsWH[j] = packH(h0, h1);
        g_opsWL[j] = packH(l0, l1);
    }
}

// ============ GEMM 1: z = x @ W_in + b_in (block 64x64, 4 warps 32x32) ============
__global__ __launch_bounds__(128) void gemm_z_tc(const float* __restrict__ bias) {
    extern __shared__ uint32_t smem[];
    const int tid = threadIdx.x, lane = tid & 31, warp = tid >> 5;
    const int wm = warp & 1, wn = warp >> 1;
    const size_t bm = blockIdx.x * TILEM;
    const int bn = blockIdx.y * 64;
    float acc[2][4][4] = {};
    stage_A2(smem, 0, g_xH, g_xL, bm, INDIM / 2, 0, tid);
    stage_B2(smem, 0, g_WinH, g_WinL, (size_t)bn, Dm, tid);
    CP_COMMIT();
    for (int k0 = 0; k0 < INDIM; k0 += 32) {
        const int s = (k0 >> 5) & 1;
        CP_WAIT0();
        __syncthreads();
        if (k0 + 32 < INDIM) {
            stage_A2(smem, s ^ 1, g_xH, g_xL, bm, INDIM / 2, (k0 + 32) / 2, tid);
            stage_B2(smem, s ^ 1, g_WinH, g_WinL, (size_t)((k0 + 32) / 2) * Dm + bn, Dm, tid);
        }
        CP_COMMIT();
        mma_k16(smem, s, wm, wn, lane, 0, acc);
        mma_k16(smem, s, wm, wn, lane, 8, acc);
        __syncthreads();
    }
    const int lr = lane >> 2, lc = lane & 3;
#pragma unroll
    for (int mt = 0; mt < 2; mt++)
#pragma unroll
        for (int nt = 0; nt < 4; nt++) {
            size_t m0 = bm + wm * 32 + mt * 16 + lr;
            int n0 = bn + wn * 32 + nt * 8 + 2 * lc;
            float b0 = bias[n0], b1 = bias[n0 + 1];
            float v00 = acc[mt][nt][0] + b0, v01 = acc[mt][nt][1] + b1;
            float v10 = acc[mt][nt][2] + b0, v11 = acc[mt][nt][3] + b1;
            g_z[m0 * Dm + n0] = v00;           g_z[m0 * Dm + n0 + 1] = v01;
            g_z[(m0 + 8) * Dm + n0] = v10;     g_z[(m0 + 8) * Dm + n0 + 1] = v11;
            __half h0, l0, h1, l1;
            splitH(v00, h0, l0); splitH(v01, h1, l1);
            g_zH[m0 * (Dm / 2) + n0 / 2] = packH(h0, h1);
            g_zL[m0 * (Dm / 2) + n0 / 2] = packH(l0, l1);
            splitH(v10, h0, l0); splitH(v11, h1, l1);
            g_zH[(m0 + 8) * (Dm / 2) + n0 / 2] = packH(h0, h1);
            g_zL[(m0 + 8) * (Dm / 2) + n0 / 2] = packH(l0, l1);
        }
}

// ======= GEMM 2: sym = z @ sym_W (fp32 out) + fused mean accumulation =======
__global__ __launch_bounds__(128) void gemm_sym_tc(float* __restrict__ symOut) {
    extern __shared__ uint32_t smem[];
    const int tid = threadIdx.x, lane = tid & 31, warp = tid >> 5;
    const int wm = warp & 1, wn = warp >> 1;
    const size_t bm = blockIdx.x * TILEM;
    const int bn = blockIdx.y * 64;
    const size_t boff = (size_t)(bn >> 7) * ((Dm / 2) * Ss) + (bn & 127);
    float acc[2][4][4] = {};
    stage_A2(smem, 0, g_zH, g_zL, bm, Dm / 2, 0, tid);
    stage_B2(smem, 0, g_symWH, g_symWL, boff, Ss, tid);
    CP_COMMIT();
    for (int k0 = 0; k0 < Dm; k0 += 32) {
        const int s = (k0 >> 5) & 1;
        CP_WAIT0();
        __syncthreads();
        if (k0 + 32 < Dm) {
            stage_A2(smem, s ^ 1, g_zH, g_zL, bm, Dm / 2, (k0 + 32) / 2, tid);
            stage_B2(smem, s ^ 1, g_symWH, g_symWL,
                     boff + (size_t)((k0 + 32) / 2) * Ss, Ss, tid);
        }
        CP_COMMIT();
        mma_k16(smem, s, wm, wn, lane, 0, acc);
        mma_k16(smem, s, wm, wn, lane, 8, acc);
        __syncthreads();
    }
    const int lr = lane >> 2, lc = lane & 3;
    const int scol = (bn & 127);
#pragma unroll
    for (int mt = 0; mt < 2; mt++)
#pragma unroll
        for (int nt = 0; nt < 4; nt++) {
            size_t m0 = bm + wm * 32 + mt * 16 + lr;
            int n0 = bn + wn * 32 + nt * 8 + 2 * lc;
            int sc = scol + wn * 32 + nt * 8 + 2 * lc;
            float v00 = acc[mt][nt][0], v01 = acc[mt][nt][1];
            float v10 = acc[mt][nt][2], v11 = acc[mt][nt][3];
            symOut[m0 * (Nn * Ss) + n0]           = v00;
            symOut[m0 * (Nn * Ss) + n0 + 1]       = v01;
            symOut[(m0 + 8) * (Nn * Ss) + n0]     = v10;
            symOut[(m0 + 8) * (Nn * Ss) + n0 + 1] = v11;
            atomicAdd(&g_symmean[m0 * Ss + sc],           0.125f * v00);
            atomicAdd(&g_symmean[m0 * Ss + sc + 1],       0.125f * v01);
            atomicAdd(&g_symmean[(m0 + 8) * Ss + sc],     0.125f * v10);
            atomicAdd(&g_symmean[(m0 + 8) * Ss + sc + 1], 0.125f * v11);
        }
}

// ====== router: compensated-fp32 split-k x4 + exact merge; argmax -> prog ======
__global__ __launch_bounds__(576) void router_kernel(
    const float* __restrict__ RW, const float* __restrict__ rb, float* __restrict__ progf) {
    __shared__ float rin[4][644];
    __shared__ float ps[4][36][4], pc[4][36][4];
    __shared__ float lg[4][36];
    const int b0 = blockIdx.x * 4;
    const int tid = threadIdx.x;
    for (int i = tid; i < 4 * 640; i += 576) {
        int t = i / 640, k = i - t * 640;
        rin[t][k] = (k < Dm) ? g_z[(size_t)(b0 + t) * Dm + k]
                             : g_symmean[(size_t)(b0 + t) * Ss + (k - Dm)];
    }
    __syncthreads();
    {
        const int t  = tid / 144;
        const int r  = tid - t * 144;
        const int j  = r % 36;
        const int ks = r / 36;
        const int kbeg = ks * 160;
        const float* rw = RW + j;
        float s0 = 0.f, s1 = 0.f, c0 = 0.f, c1 = 0.f;
#pragma unroll 4
        for (int k = kbeg; k < kbeg + 160; k += 2) {
            {
                float x = rin[t][k];
                float w = __ldg(&rw[k * 36]);
                float p = __fmul_rn(x, w);
                float e = __fmaf_rn(x, w, -p);
                float S, er; two_sum(s0, p, S, er);
                s0 = S; c0 = __fadd_rn(c0, __fadd_rn(er, e));
            }
            {
                float x = rin[t][k + 1];
                float w = __ldg(&rw[(k + 1) * 36]);
                float p = __fmul_rn(x, w);
                float e = __fmaf_rn(x, w, -p);
                float S, er; two_sum(s1, p, S, er);
                s1 = S; c1 = __fadd_rn(c1, __fadd_rn(er, e));
            }
        }
        float S, er; two_sum(s0, s1, S, er);
        ps[t][j][ks] = S;
        pc[t][j][ks] = __fadd_rn(c0, __fadd_rn(c1, er));
    }
    __syncthreads();
    if (tid < 144) {
        int t = tid / 36, j = tid - t * 36;
        float S = ps[t][j][0], C = pc[t][j][0];
#pragma unroll
        for (int ks = 1; ks < 4; ks++) {
            float S2, er; two_sum(S, ps[t][j][ks], S2, er);
            S = S2;
            C = __fadd_rn(C, __fadd_rn(er, pc[t][j][ks]));
        }
        float S2, er; two_sum(S, rb[j], S2, er);
        lg[t][j] = __fadd_rn(S2, __fadd_rn(C, er));
    }
    __syncthreads();
    if (tid < 16) {
        int t = tid >> 2, h = tid & 3;
        const float* l = &lg[t][h * 9];
        float best = l[0]; int bi = 0;
#pragma unroll
        for (int j = 1; j < 9; j++)
            if (l[j] > best) { best = l[j]; bi = j; }   // first-max tie-break
        g_prog[(b0 + t) * HOPS + h] = bi;
        progf[(b0 + t) * HOPS + h] = (float)bi;
    }
}

// ======= schedule: group active tokens by (hop, expert); 64-row tiles =======
__global__ void schedule_kernel() {
    __shared__ int cnt[HOPS][Nn];
    __shared__ int cur[HOPS][Nn];
    const int tid = threadIdx.x;
    if (tid < HOPS * Nn) cnt[tid / Nn][tid % Nn] = 0;
    __syncthreads();
    for (int b = tid; b < Bsz; b += blockDim.x) {
        bool act = true;
        for (int t = 0; t < HOPS; t++) {
            int e = g_prog[b * HOPS + t];
            act = act && (e != Nn);
            if (act) atomicAdd(&cnt[t][e], 1);
        }
    }
    __syncthreads();
    if (tid < HOPS) {
        int t = tid, p = 0, nt = 0;
        for (int e = 0; e < Nn; e++) {
            cur[t][e] = p;
            int c = cnt[t][e], q = p;
            while (c > 0) {
                g_tileE[t][nt] = e; g_tileS[t][nt] = q;
                g_tileC[t][nt] = (c < TILEM) ? c : TILEM;
                q += TILEM; c -= TILEM; nt++;
            }
            p += cnt[t][e];
        }
        g_numTiles[t] = nt;
    }
    __syncthreads();
    for (int b = tid; b < Bsz; b += blockDim.x) {
        bool act = true;
        for (int t = 0; t < HOPS; t++) {
            int e = g_prog[b * HOPS + t];
            act = act && (e != Nn);
            if (act) { int p = atomicAdd(&cur[t][e], 1); g_order[t][p] = b; }
        }
    }
}

// == hop: dst planes[tok] = split(gelu(src[tok] @ ops_W[e] + ops_b[e])) ==
// No inter-hop copies: active(h+1) ⊆ active(h). Outputs stored only as hi/lo planes.
__global__ __launch_bounds__(128) void hop_tc(
    int hop, int srcSel, const float* __restrict__ opsB) {
    if ((int)blockIdx.x >= g_numTiles[hop]) return;
    extern __shared__ uint32_t smem[];
    __shared__ int toks[TILEM];
    const uint32_t* srcH = (srcSel == 0) ? g_zH : g_bufH;
    const uint32_t* srcL = (srcSel == 0) ? g_zL : g_bufL;
    uint32_t* dstH = (srcSel == 0) ? g_bufH : g_zH;
    uint32_t* dstL = (srcSel == 0) ? g_bufL : g_zL;
    const int e     = g_tileE[hop][blockIdx.x];
    const int start = g_tileS[hop][blockIdx.x];
    const int cnt   = g_tileC[hop][blockIdx.x];
    const int bn    = blockIdx.y * 64;
    const int tid = threadIdx.x, lane = tid & 31, warp = tid >> 5;
    const int wm = warp & 1, wn = warp >> 1;
    if (tid < TILEM) toks[tid] = (tid < cnt) ? g_order[hop][start + tid] : -1;
    __syncthreads();
    const uint32_t* WH = g_opsWH + (size_t)e * ((Dm / 2) * Dm);
    const uint32_t* WL = g_opsWL + (size_t)e * ((Dm / 2) * Dm);
    const int myTok = toks[tid >> 1];
    stage_A2g(smem, 0, srcH, srcL, myTok, 0, tid);
    stage_B2(smem, 0, WH, WL, (size_t)bn, Dm, tid);
    CP_COMMIT();
    float acc[2][4][4] = {};
    for (int k0 = 0; k0 < Dm; k0 += 32) {
        const int s = (k0 >> 5) & 1;
        CP_WAIT0();
        __syncthreads();
        if (k0 + 32 < Dm) {
            stage_A2g(smem, s ^ 1, srcH, srcL, myTok, (k0 + 32) / 2, tid);
            stage_B2(smem, s ^ 1, WH, WL, (size_t)((k0 + 32) / 2) * Dm + bn, Dm, tid);
        }
        CP_COMMIT();
        mma_k16(smem, s, wm, wn, lane, 0, acc);
        mma_k16(smem, s, wm, wn, lane, 8, acc);
        __syncthreads();
    }
    const int lr = lane >> 2, lc = lane & 3;
#pragma unroll
    for (int mt = 0; mt < 2; mt++) {
        int r0 = wm * 32 + mt * 16 + lr;
        int tk0 = toks[r0], tk1 = toks[r0 + 8];
#pragma unroll
        for (int nt = 0; nt < 4; nt++) {
            int n0 = bn + wn * 32 + nt * 8 + 2 * lc;
            float b0 = opsB[e * Dm + n0], b1 = opsB[e * Dm + n0 + 1];
            if (tk0 >= 0) {
                float v0 = gelu_tanh(acc[mt][nt][0] + b0);
                float v1 = gelu_tanh(acc[mt][nt][1] + b1);
                __half h0, l0, h1, l1;
                splitH(v0, h0, l0); splitH(v1, h1, l1);
                dstH[(size_t)tk0 * (Dm / 2) + n0 / 2] = packH(h0, h1);
                dstL[(size_t)tk0 * (Dm / 2) + n0 / 2] = packH(l0, l1);
            }
            if (tk1 >= 0) {
                float v0 = gelu_tanh(acc[mt][nt][2] + b0);
                float v1 = gelu_tanh(acc[mt][nt][3] + b1);
                __half h0, l0, h1, l1;
                splitH(v0, h0, l0); splitH(v1, h1, l1);
                dstH[(size_t)tk1 * (Dm / 2) + n0 / 2] = packH(h0, h1);
                dstL[(size_t)tk1 * (Dm / 2) + n0 / 2] = packH(l0, l1);
            }
        }
    }
}

// ===== final gather: reconstruct fp32 out from the parity-selected plane pair =====
__global__ void gather_out(float* __restrict__ out) {
    int idx = blockIdx.x * blockDim.x + threadIdx.x;   // over Bsz*Dm/2 words
    int b = idx >> 8;
    int nact = 0;
#pragma unroll
    for (int t = 0; t < HOPS; t++) {
        if (g_prog[b * HOPS + t] == Nn) break;
        nact++;
    }
    const uint32_t* sH = (nact & 1) ? g_bufH : g_zH;
    const uint32_t* sL = (nact & 1) ? g_bufL : g_zL;
    uint32_t wh = sH[idx], wl = sL[idx];
    __half2 h = *reinterpret_cast<__half2*>(&wh);
    __half2 l = *reinterpret_cast<__half2*>(&wl);
    float2 o;
    o.x = __fadd_rn(__half2float(__low2half(h)),  __half2float(__low2half(l)));
    o.y = __fadd_rn(__half2float(__high2half(h)), __half2float(__high2half(l)));
    reinterpret_cast<float2*>(out)[idx] = o;
}

// =========================== launch ===========================
extern "C" void kernel_launch(void* const* d_in, const int* in_sizes, int n_in,
                              void* d_out, int out_size) {
    const float* x        = (const float*)d_in[0];
    const float* W_in     = (const float*)d_in[1];
    const float* b_in     = (const float*)d_in[2];
    const float* ops_W    = (const float*)d_in[3];
    const float* ops_b    = (const float*)d_in[4];
    const float* sym_W    = (const float*)d_in[5];
    const float* router_W = (const float*)d_in[6];
    const float* router_b = (const float*)d_in[7];
    (void)in_sizes; (void)n_in; (void)out_size;

    float* out   = (float*)d_out;                 // [B, D]
    float* progf = out + Bsz * Dm;                // [B, HOPS] as float
    float* sym   = progf + Bsz * HOPS;            // [B, N, S]

    cudaFuncSetAttribute(gemm_z_tc,   cudaFuncAttributeMaxDynamicSharedMemorySize, SMEM_BYTES);
    cudaFuncSetAttribute(gemm_sym_tc, cudaFuncAttributeMaxDynamicSharedMemorySize, SMEM_BYTES);
    cudaFuncSetAttribute(hop_tc,      cudaFuncAttributeMaxDynamicSharedMemorySize, SMEM_BYTES);

    zero_mean <<<(Bsz * Ss / 4) / 256, 256>>>();
    split_all <<<NALL / 256, 256>>>(x, W_in, sym_W, ops_W);

    gemm_z_tc   <<<dim3(Bsz / TILEM, Dm / 64), 128, SMEM_BYTES>>>(b_in);
    gemm_sym_tc <<<dim3(Bsz / TILEM, (Nn * Ss) / 64), 128, SMEM_BYTES>>>(sym);  // 4th: profiled
    router_kernel<<<Bsz / 4, 576>>>(router_W, router_b, progf);
    schedule_kernel<<<1, 512>>>();

    hop_tc<<<dim3(MAXT, Dm / 64), 128, SMEM_BYTES>>>(0, 0, ops_b);  // z   -> buf
    hop_tc<<<dim3(MAXT, Dm / 64), 128, SMEM_BYTES>>>(1, 1, ops_b);  // buf -> z
    hop_tc<<<dim3(MAXT, Dm / 64), 128, SMEM_BYTES>>>(2, 0, ops_b);  // z   -> buf
    hop_tc<<<dim3(MAXT, Dm / 64), 128, SMEM_BYTES>>>(3, 1, ops_b);  // buf -> z

    gather_out<<<(Bsz * Dm / 2) / 256, 256>>>(out);
}

// round 14
// speedup vs baseline: 1.3910x; 1.1274x over previous
#include <cuda_runtime.h>
#include <cuda_fp16.h>
#include <math.h>
#include <stdint.h>

// Problem constants (fixed by the reference)
#define Bsz   4096
#define INDIM 1024
#define Dm    512
#define Nn    8
#define Ss    128
#define HOPS  4
#define TILEM 64
#define MAXT  72      // max token tiles per hop: 4096/64 + 8

// packed-plane geometry (K dims packed by pairs into half2 words)
#define A_ST2 20      // A smem stride (words): frag banks (4*lr+lc style) distinct
#define B_ST2 136     // B smem stride: 136 mod 32 == 8 -> banks (8*lc+lr) distinct
// dynamic smem (words), tile 64(M) x 128(N):
//   A stage s: hi [64][20] @ s*2560, lo @ +1280            (2560/stage)
//   B stage s: hi [16][136] @ 5120 + s*4352, lo @ +2176    (4352/stage)
#define SMEM_WORDS 13824
#define SMEM_BYTES (SMEM_WORDS * 4)   // 55296

// split_all ranges
#define NX    (Bsz * INDIM / 2)
#define NWIN  ((INDIM / 2) * Dm)
#define NSYM  (Nn * (Dm / 2) * Ss)
#define NOPS  (Nn * (Dm / 2) * Dm)
#define NALL  (NX + NWIN + NSYM + NOPS)

// -------- device scratch --------
__device__ float    g_z[Bsz * Dm];
__device__ float    g_symmean[Bsz * Ss];
__device__ int      g_prog[Bsz * HOPS];
__device__ int      g_order[HOPS][Bsz];
__device__ int      g_tileE[HOPS][MAXT];
__device__ int      g_tileS[HOPS][MAXT];
__device__ int      g_tileC[HOPS][MAXT];
__device__ int      g_numTiles[HOPS];
__device__ uint32_t g_xH[Bsz * INDIM / 2],  g_xL[Bsz * INDIM / 2];
__device__ uint32_t g_zH[Bsz * Dm / 2],     g_zL[Bsz * Dm / 2];
__device__ uint32_t g_bufH[Bsz * Dm / 2],   g_bufL[Bsz * Dm / 2];
__device__ uint32_t g_WinH[(INDIM / 2) * Dm],  g_WinL[(INDIM / 2) * Dm];
__device__ uint32_t g_symWH[Nn * (Dm / 2) * Ss], g_symWL[Nn * (Dm / 2) * Ss];
__device__ uint32_t g_opsWH[Nn * (Dm / 2) * Dm], g_opsWL[Nn * (Dm / 2) * Dm];

__device__ __forceinline__ float gelu_tanh(float x) {
    float x3 = x * x * x;
    return 0.5f * x * (1.0f + tanhf(0.7978845608028654f * (x + 0.044715f * x3)));
}
__device__ __forceinline__ void splitH(float v, __half& h, __half& l) {
    h = __float2half_rn(v);
    l = __float2half_rn(__fsub_rn(v, __half2float(h)));
}
__device__ __forceinline__ uint32_t packH(__half a, __half b) {
    __half2 p = __halves2half2(a, b);
    return *reinterpret_cast<uint32_t*>(&p);
}
__device__ __forceinline__ void two_sum(float a, float b, float& s, float& e) {
    s = __fadd_rn(a, b);
    float bv = __fsub_rn(s, a);
    e = __fadd_rn(__fsub_rn(a, __fsub_rn(s, bv)), __fsub_rn(b, bv));
}

#define MMAF16(d, a, b)                                                       \
    asm("mma.sync.aligned.m16n8k16.row.col.f32.f16.f16.f32 "                  \
        "{%0,%1,%2,%3}, {%4,%5,%6,%7}, {%8,%9}, {%0,%1,%2,%3};"               \
        : "+f"(d[0]), "+f"(d[1]), "+f"(d[2]), "+f"(d[3])                      \
        : "r"(a[0]), "r"(a[1]), "r"(a[2]), "r"(a[3]), "r"(b[0]), "r"(b[1]))

__device__ __forceinline__ void cp_async16(uint32_t saddr, const void* g) {
    asm volatile("cp.async.cg.shared.global [%0], [%1], 16;" :: "r"(saddr), "l"(g));
}
__device__ __forceinline__ void cp_async16_z(uint32_t saddr, const void* g, int srcsz) {
    asm volatile("cp.async.cg.shared.global [%0], [%1], 16, %2;"
                 :: "r"(saddr), "l"(g), "r"(srcsz));
}
#define CP_COMMIT() asm volatile("cp.async.commit_group;")
#define CP_WAIT0()  asm volatile("cp.async.wait_group 0;" ::: "memory")

// Stage A slab: 64 rows x 16 words, hi+lo planes. 256 threads (2 chunks each).
__device__ __forceinline__ void stage_A2(uint32_t* smem, int s,
                                         const uint32_t* __restrict__ GH,
                                         const uint32_t* __restrict__ GL,
                                         size_t row0, int ldw, int k2col, int tid) {
    const int plane = tid & 1;
    const int rr = tid >> 1;           // 0..127
    const int row = rr & 63;
    const int c0 = (rr >> 6) * 8;      // word col: 0 or 8
    const uint32_t* G = plane ? GL : GH;
    uint32_t base = (uint32_t)__cvta_generic_to_shared(smem + s * 2560 + plane * 1280);
    const uint32_t so = (uint32_t)(row * A_ST2 + c0) * 4;
    const uint32_t* src = G + (row0 + row) * ldw + k2col + c0;
    cp_async16(base + so,      src);
    cp_async16(base + so + 16, src + 4);
}

// Stage A with token gather (hop). tok<0 rows zero-filled.
__device__ __forceinline__ void stage_A2g(uint32_t* smem, int s,
                                          const uint32_t* __restrict__ GH,
                                          const uint32_t* __restrict__ GL,
                                          int tok, int k2col, int tid) {
    const int plane = tid & 1;
    const int rr = tid >> 1;
    const int row = rr & 63;
    const int c0 = (rr >> 6) * 8;
    const uint32_t* G = plane ? GL : GH;
    uint32_t base = (uint32_t)__cvta_generic_to_shared(smem + s * 2560 + plane * 1280);
    const uint32_t so = (uint32_t)(row * A_ST2 + c0) * 4;
    size_t grow = (size_t)(tok < 0 ? 0 : tok);
    int sz = tok < 0 ? 0 : 16;
    const uint32_t* src = G + grow * (Dm / 2) + k2col + c0;
    cp_async16_z(base + so,      src,     sz);
    cp_async16_z(base + so + 16, src + 4, sz);
}

// Stage B slab: 16 k2-rows x 128 n-words, hi+lo. 256 threads (4 cp16 each).
__device__ __forceinline__ void stage_B2(uint32_t* smem, int s,
                                         const uint32_t* __restrict__ GH,
                                         const uint32_t* __restrict__ GL,
                                         size_t gbase, int ldw, int tid) {
    uint32_t base_h = (uint32_t)__cvta_generic_to_shared(smem + 5120 + s * 4352);
    uint32_t base_l = base_h + 2176 * 4;
#pragma unroll
    for (int p = 0; p < 2; p++) {
        int q = tid + p * 256;          // 0..511
        int row = q >> 5, col = (q & 31) * 4;
        uint32_t soff = (uint32_t)(row * B_ST2 + col) * 4;
        size_t goff = gbase + (size_t)row * ldw + col;
        cp_async16(base_h + soff, GH + goff);
        cp_async16(base_l + soff, GL + goff);
    }
}

// One k16 step: warp (wm, wn in 0..3) computes 32x32, 3xFP16.
__device__ __forceinline__ void mma_k16(
    const uint32_t* __restrict__ smem, int s, int wm, int wn, int lane, int k2off,
    float acc[2][4][4]) {
    const uint32_t* AhS = smem + s * 2560;
    const uint32_t* AlS = AhS + 1280;
    const uint32_t* BhS = smem + 5120 + s * 4352;
    const uint32_t* BlS = BhS + 2176;
    const int lr = lane >> 2, lc = lane & 3;
    uint32_t ah[2][4], al[2][4];
#pragma unroll
    for (int mt = 0; mt < 2; mt++) {
        int m = wm * 32 + mt * 16 + lr;
        ah[mt][0] = AhS[m * A_ST2 + k2off + lc];
        ah[mt][1] = AhS[(m + 8) * A_ST2 + k2off + lc];
        ah[mt][2] = AhS[m * A_ST2 + k2off + 4 + lc];
        ah[mt][3] = AhS[(m + 8) * A_ST2 + k2off + 4 + lc];
        al[mt][0] = AlS[m * A_ST2 + k2off + lc];
        al[mt][1] = AlS[(m + 8) * A_ST2 + k2off + lc];
        al[mt][2] = AlS[m * A_ST2 + k2off + 4 + lc];
        al[mt][3] = AlS[(m + 8) * A_ST2 + k2off + 4 + lc];
    }
#pragma unroll
    for (int nt = 0; nt < 4; nt++) {
        int n = wn * 32 + nt * 8 + lr;
        uint32_t bh[2], bl[2];
        bh[0] = BhS[(k2off + lc) * B_ST2 + n];
        bh[1] = BhS[(k2off + 4 + lc) * B_ST2 + n];
        bl[0] = BlS[(k2off + lc) * B_ST2 + n];
        bl[1] = BlS[(k2off + 4 + lc) * B_ST2 + n];
#pragma unroll
        for (int mt = 0; mt < 2; mt++) {
            MMAF16(acc[mt][nt], ah[mt], bl);
            MMAF16(acc[mt][nt], al[mt], bh);
            MMAF16(acc[mt][nt], ah[mt], bh);
        }
    }
}

// ============ zero g_symmean ============
__global__ void zero_mean() {
    int i = blockIdx.x * blockDim.x + threadIdx.x;
    reinterpret_cast<float4*>(g_symmean)[i] = make_float4(0.f, 0.f, 0.f, 0.f);
}

// ============ fused pre-split ============
__global__ void split_all(const float* __restrict__ x, const float* __restrict__ Win,
                          const float* __restrict__ symW, const float* __restrict__ opsW) {
    int i = blockIdx.x * blockDim.x + threadIdx.x;
    __half h0, l0, h1, l1;
    if (i < NX) {
        float2 v = reinterpret_cast<const float2*>(x)[i];
        splitH(v.x, h0, l0); splitH(v.y, h1, l1);
        g_xH[i] = packH(h0, h1);
        g_xL[i] = packH(l0, l1);
    } else if (i < NX + NWIN) {
        int j = i - NX;
        int r2 = j / Dm, c = j - r2 * Dm;
        float f0 = Win[(size_t)(2 * r2) * Dm + c];
        float f1 = Win[(size_t)(2 * r2 + 1) * Dm + c];
        splitH(f0, h0, l0); splitH(f1, h1, l1);
        g_WinH[j] = packH(h0, h1);
        g_WinL[j] = packH(l0, l1);
    } else if (i < NX + NWIN + NSYM) {
        int j = i - NX - NWIN;
        int r2 = j / Ss, c = j - r2 * Ss;
        float f0 = symW[(size_t)(2 * r2) * Ss + c];
        float f1 = symW[(size_t)(2 * r2 + 1) * Ss + c];
        splitH(f0, h0, l0); splitH(f1, h1, l1);
        g_symWH[j] = packH(h0, h1);
        g_symWL[j] = packH(l0, l1);
    } else {
        int j = i - NX - NWIN - NSYM;
        int r2 = j / Dm, c = j - r2 * Dm;
        float f0 = opsW[(size_t)(2 * r2) * Dm + c];
        float f1 = opsW[(size_t)(2 * r2 + 1) * Dm + c];
        splitH(f0, h0, l0); splitH(f1, h1, l1);
        g_opsWH[j] = packH(h0, h1);
        g_opsWL[j] = packH(l0, l1);
    }
}

// ============ GEMM 1: z = x @ W_in + b_in (tile 64x128, 8 warps) ============
__global__ __launch_bounds__(256) void gemm_z_tc(const float* __restrict__ bias) {
    extern __shared__ uint32_t smem[];
    const int tid = threadIdx.x, lane = tid & 31, warp = tid >> 5;
    const int wm = warp & 1, wn = warp >> 1;
    const size_t bm = blockIdx.x * TILEM;
    const int bn = blockIdx.y * 128;
    float acc[2][4][4] = {};
    stage_A2(smem, 0, g_xH, g_xL, bm, INDIM / 2, 0, tid);
    stage_B2(smem, 0, g_WinH, g_WinL, (size_t)bn, Dm, tid);
    CP_COMMIT();
    for (int k0 = 0; k0 < INDIM; k0 += 32) {
        const int s = (k0 >> 5) & 1;
        CP_WAIT0();
        __syncthreads();
        if (k0 + 32 < INDIM) {
            stage_A2(smem, s ^ 1, g_xH, g_xL, bm, INDIM / 2, (k0 + 32) / 2, tid);
            stage_B2(smem, s ^ 1, g_WinH, g_WinL, (size_t)((k0 + 32) / 2) * Dm + bn, Dm, tid);
        }
        CP_COMMIT();
        mma_k16(smem, s, wm, wn, lane, 0, acc);
        mma_k16(smem, s, wm, wn, lane, 8, acc);
        __syncthreads();
    }
    const int lr = lane >> 2, lc = lane & 3;
#pragma unroll
    for (int mt = 0; mt < 2; mt++)
#pragma unroll
        for (int nt = 0; nt < 4; nt++) {
            size_t m0 = bm + wm * 32 + mt * 16 + lr;
            int n0 = bn + wn * 32 + nt * 8 + 2 * lc;
            float b0 = bias[n0], b1 = bias[n0 + 1];
            float v00 = acc[mt][nt][0] + b0, v01 = acc[mt][nt][1] + b1;
            float v10 = acc[mt][nt][2] + b0, v11 = acc[mt][nt][3] + b1;
            g_z[m0 * Dm + n0] = v00;           g_z[m0 * Dm + n0 + 1] = v01;
            g_z[(m0 + 8) * Dm + n0] = v10;     g_z[(m0 + 8) * Dm + n0 + 1] = v11;
            __half h0, l0, h1, l1;
            splitH(v00, h0, l0); splitH(v01, h1, l1);
            g_zH[m0 * (Dm / 2) + n0 / 2] = packH(h0, h1);
            g_zL[m0 * (Dm / 2) + n0 / 2] = packH(l0, l1);
            splitH(v10, h0, l0); splitH(v11, h1, l1);
            g_zH[(m0 + 8) * (Dm / 2) + n0 / 2] = packH(h0, h1);
            g_zL[(m0 + 8) * (Dm / 2) + n0 / 2] = packH(l0, l1);
        }
}

// ======= GEMM 2: sym = z @ sym_W + fused mean (tile 64x128: one n_id/block) =======
__global__ __launch_bounds__(256) void gemm_sym_tc(float* __restrict__ symOut) {
    extern __shared__ uint32_t smem[];
    const int tid = threadIdx.x, lane = tid & 31, warp = tid >> 5;
    const int wm = warp & 1, wn = warp >> 1;
    const size_t bm = blockIdx.x * TILEM;
    const int bn = blockIdx.y * 128;                     // == n_id*128
    const size_t boff = (size_t)blockIdx.y * ((Dm / 2) * Ss);
    float acc[2][4][4] = {};
    stage_A2(smem, 0, g_zH, g_zL, bm, Dm / 2, 0, tid);
    stage_B2(smem, 0, g_symWH, g_symWL, boff, Ss, tid);
    CP_COMMIT();
    for (int k0 = 0; k0 < Dm; k0 += 32) {
        const int s = (k0 >> 5) & 1;
        CP_WAIT0();
        __syncthreads();
        if (k0 + 32 < Dm) {
            stage_A2(smem, s ^ 1, g_zH, g_zL, bm, Dm / 2, (k0 + 32) / 2, tid);
            stage_B2(smem, s ^ 1, g_symWH, g_symWL,
                     boff + (size_t)((k0 + 32) / 2) * Ss, Ss, tid);
        }
        CP_COMMIT();
        mma_k16(smem, s, wm, wn, lane, 0, acc);
        mma_k16(smem, s, wm, wn, lane, 8, acc);
        __syncthreads();
    }
    const int lr = lane >> 2, lc = lane & 3;
#pragma unroll
    for (int mt = 0; mt < 2; mt++)
#pragma unroll
        for (int nt = 0; nt < 4; nt++) {
            size_t m0 = bm + wm * 32 + mt * 16 + lr;
            int n0 = bn + wn * 32 + nt * 8 + 2 * lc;
            int sc = wn * 32 + nt * 8 + 2 * lc;
            float v00 = acc[mt][nt][0], v01 = acc[mt][nt][1];
            float v10 = acc[mt][nt][2], v11 = acc[mt][nt][3];
            symOut[m0 * (Nn * Ss) + n0]           = v00;
            symOut[m0 * (Nn * Ss) + n0 + 1]       = v01;
            symOut[(m0 + 8) * (Nn * Ss) + n0]     = v10;
            symOut[(m0 + 8) * (Nn * Ss) + n0 + 1] = v11;
            atomicAdd(&g_symmean[m0 * Ss + sc],           0.125f * v00);
            atomicAdd(&g_symmean[m0 * Ss + sc + 1],       0.125f * v01);
            atomicAdd(&g_symmean[(m0 + 8) * Ss + sc],     0.125f * v10);
            atomicAdd(&g_symmean[(m0 + 8) * Ss + sc + 1], 0.125f * v11);
        }
}

// ====== router: compensated-fp32 split-k x4 + exact merge; argmax -> prog ======
__global__ __launch_bounds__(576) void router_kernel(
    const float* __restrict__ RW, const float* __restrict__ rb, float* __restrict__ progf) {
    __shared__ float rin[4][644];
    __shared__ float ps[4][36][4], pc[4][36][4];
    __shared__ float lg[4][36];
    const int b0 = blockIdx.x * 4;
    const int tid = threadIdx.x;
    for (int i = tid; i < 4 * 640; i += 576) {
        int t = i / 640, k = i - t * 640;
        rin[t][k] = (k < Dm) ? g_z[(size_t)(b0 + t) * Dm + k]
                             : g_symmean[(size_t)(b0 + t) * Ss + (k - Dm)];
    }
    __syncthreads();
    {
        const int t  = tid / 144;
        const int r  = tid - t * 144;
        const int j  = r % 36;
        const int ks = r / 36;
        const int kbeg = ks * 160;
        const float* rw = RW + j;
        float s0 = 0.f, s1 = 0.f, c0 = 0.f, c1 = 0.f;
#pragma unroll 4
        for (int k = kbeg; k < kbeg + 160; k += 2) {
            {
                float x = rin[t][k];
                float w = __ldg(&rw[k * 36]);
                float p = __fmul_rn(x, w);
                float e = __fmaf_rn(x, w, -p);
                float S, er; two_sum(s0, p, S, er);
                s0 = S; c0 = __fadd_rn(c0, __fadd_rn(er, e));
            }
            {
                float x = rin[t][k + 1];
                float w = __ldg(&rw[(k + 1) * 36]);
                float p = __fmul_rn(x, w);
                float e = __fmaf_rn(x, w, -p);
                float S, er; two_sum(s1, p, S, er);
                s1 = S; c1 = __fadd_rn(c1, __fadd_rn(er, e));
            }
        }
        float S, er; two_sum(s0, s1, S, er);
        ps[t][j][ks] = S;
        pc[t][j][ks] = __fadd_rn(c0, __fadd_rn(c1, er));
    }
    __syncthreads();
    if (tid < 144) {
        int t = tid / 36, j = tid - t * 36;
        float S = ps[t][j][0], C = pc[t][j][0];
#pragma unroll
        for (int ks = 1; ks < 4; ks++) {
            float S2, er; two_sum(S, ps[t][j][ks], S2, er);
            S = S2;
            C = __fadd_rn(C, __fadd_rn(er, pc[t][j][ks]));
        }
        float S2, er; two_sum(S, rb[j], S2, er);
        lg[t][j] = __fadd_rn(S2, __fadd_rn(C, er));
    }
    __syncthreads();
    if (tid < 16) {
        int t = tid >> 2, h = tid & 3;
        const float* l = &lg[t][h * 9];
        float best = l[0]; int bi = 0;
#pragma unroll
        for (int j = 1; j < 9; j++)
            if (l[j] > best) { best = l[j]; bi = j; }
        g_prog[(b0 + t) * HOPS + h] = bi;
        progf[(b0 + t) * HOPS + h] = (float)bi;
    }
}

// ======= schedule: group active tokens by (hop, expert); 64-row tiles =======
__global__ void schedule_kernel() {
    __shared__ int cnt[HOPS][Nn];
    __shared__ int cur[HOPS][Nn];
    const int tid = threadIdx.x;
    if (tid < HOPS * Nn) cnt[tid / Nn][tid % Nn] = 0;
    __syncthreads();
    for (int b = tid; b < Bsz; b += blockDim.x) {
        bool act = true;
        for (int t = 0; t < HOPS; t++) {
            int e = g_prog[b * HOPS + t];
            act = act && (e != Nn);
            if (act) atomicAdd(&cnt[t][e], 1);
        }
    }
    __syncthreads();
    if (tid < HOPS) {
        int t = tid, p = 0, nt = 0;
        for (int e = 0; e < Nn; e++) {
            cur[t][e] = p;
            int c = cnt[t][e], q = p;
            while (c > 0) {
                g_tileE[t][nt] = e; g_tileS[t][nt] = q;
                g_tileC[t][nt] = (c < TILEM) ? c : TILEM;
                q += TILEM; c -= TILEM; nt++;
            }
            p += cnt[t][e];
        }
        g_numTiles[t] = nt;
    }
    __syncthreads();
    for (int b = tid; b < Bsz; b += blockDim.x) {
        bool act = true;
        for (int t = 0; t < HOPS; t++) {
            int e = g_prog[b * HOPS + t];
            act = act && (e != Nn);
            if (act) { int p = atomicAdd(&cur[t][e], 1); g_order[t][p] = b; }
        }
    }
}

// == hop: dst planes[tok] = split(gelu(src[tok] @ ops_W[e] + b)), tile 64x128 ==
__global__ __launch_bounds__(256) void hop_tc(
    int hop, int srcSel, const float* __restrict__ opsB) {
    if ((int)blockIdx.x >= g_numTiles[hop]) return;
    extern __shared__ uint32_t smem[];
    __shared__ int toks[TILEM];
    const uint32_t* srcH = (srcSel == 0) ? g_zH : g_bufH;
    const uint32_t* srcL = (srcSel == 0) ? g_zL : g_bufL;
    uint32_t* dstH = (srcSel == 0) ? g_bufH : g_zH;
    uint32_t* dstL = (srcSel == 0) ? g_bufL : g_zL;
    const int e     = g_tileE[hop][blockIdx.x];
    const int start = g_tileS[hop][blockIdx.x];
    const int cnt   = g_tileC[hop][blockIdx.x];
    const int bn    = blockIdx.y * 128;
    const int tid = threadIdx.x, lane = tid & 31, warp = tid >> 5;
    const int wm = warp & 1, wn = warp >> 1;
    if (tid < TILEM) toks[tid] = (tid < cnt) ? g_order[hop][start + tid] : -1;
    __syncthreads();
    const uint32_t* WH = g_opsWH + (size_t)e * ((Dm / 2) * Dm);
    const uint32_t* WL = g_opsWL + (size_t)e * ((Dm / 2) * Dm);
    const int myTok = toks[(tid >> 1) & 63];
    stage_A2g(smem, 0, srcH, srcL, myTok, 0, tid);
    stage_B2(smem, 0, WH, WL, (size_t)bn, Dm, tid);
    CP_COMMIT();
    float acc[2][4][4] = {};
    for (int k0 = 0; k0 < Dm; k0 += 32) {
        const int s = (k0 >> 5) & 1;
        CP_WAIT0();
        __syncthreads();
        if (k0 + 32 < Dm) {
            stage_A2g(smem, s ^ 1, srcH, srcL, myTok, (k0 + 32) / 2, tid);
            stage_B2(smem, s ^ 1, WH, WL, (size_t)((k0 + 32) / 2) * Dm + bn, Dm, tid);
        }
        CP_COMMIT();
        mma_k16(smem, s, wm, wn, lane, 0, acc);
        mma_k16(smem, s, wm, wn, lane, 8, acc);
        __syncthreads();
    }
    const int lr = lane >> 2, lc = lane & 3;
#pragma unroll
    for (int mt = 0; mt < 2; mt++) {
        int r0 = wm * 32 + mt * 16 + lr;
        int tk0 = toks[r0], tk1 = toks[r0 + 8];
#pragma unroll
        for (int nt = 0; nt < 4; nt++) {
            int n0 = bn + wn * 32 + nt * 8 + 2 * lc;
            float b0 = opsB[e * Dm + n0], b1 = opsB[e * Dm + n0 + 1];
            if (tk0 >= 0) {
                float v0 = gelu_tanh(acc[mt][nt][0] + b0);
                float v1 = gelu_tanh(acc[mt][nt][1] + b1);
                __half h0, l0, h1, l1;
                splitH(v0, h0, l0); splitH(v1, h1, l1);
                dstH[(size_t)tk0 * (Dm / 2) + n0 / 2] = packH(h0, h1);
                dstL[(size_t)tk0 * (Dm / 2) + n0 / 2] = packH(l0, l1);
            }
            if (tk1 >= 0) {
                float v0 = gelu_tanh(acc[mt][nt][2] + b0);
                float v1 = gelu_tanh(acc[mt][nt][3] + b1);
                __half h0, l0, h1, l1;
                splitH(v0, h0, l0); splitH(v1, h1, l1);
                dstH[(size_t)tk1 * (Dm / 2) + n0 / 2] = packH(h0, h1);
                dstL[(size_t)tk1 * (Dm / 2) + n0 / 2] = packH(l0, l1);
            }
        }
    }
}

// ===== final gather =====
__global__ void gather_out(float* __restrict__ out) {
    int idx = blockIdx.x * blockDim.x + threadIdx.x;
    int b = idx >> 8;
    int nact = 0;
#pragma unroll
    for (int t = 0; t < HOPS; t++) {
        if (g_prog[b * HOPS + t] == Nn) break;
        nact++;
    }
    const uint32_t* sH = (nact & 1) ? g_bufH : g_zH;
    const uint32_t* sL = (nact & 1) ? g_bufL : g_zL;
    uint32_t wh = sH[idx], wl = sL[idx];
    __half2 h = *reinterpret_cast<__half2*>(&wh);
    __half2 l = *reinterpret_cast<__half2*>(&wl);
    float2 o;
    o.x = __fadd_rn(__half2float(__low2half(h)),  __half2float(__low2half(l)));
    o.y = __fadd_rn(__half2float(__high2half(h)), __half2float(__high2half(l)));
    reinterpret_cast<float2*>(out)[idx] = o;
}

// =========================== launch ===========================
extern "C" void kernel_launch(void* const* d_in, const int* in_sizes, int n_in,
                              void* d_out, int out_size) {
    const float* x        = (const float*)d_in[0];
    const float* W_in     = (const float*)d_in[1];
    const float* b_in     = (const float*)d_in[2];
    const float* ops_W    = (const float*)d_in[3];
    const float* ops_b    = (const float*)d_in[4];
    const float* sym_W    = (const float*)d_in[5];
    const float* router_W = (const float*)d_in[6];
    const float* router_b = (const float*)d_in[7];
    (void)in_sizes; (void)n_in; (void)out_size;

    float* out   = (float*)d_out;
    float* progf = out + Bsz * Dm;
    float* sym   = progf + Bsz * HOPS;

    cudaFuncSetAttribute(gemm_z_tc,   cudaFuncAttributeMaxDynamicSharedMemorySize, SMEM_BYTES);
    cudaFuncSetAttribute(gemm_sym_tc, cudaFuncAttributeMaxDynamicSharedMemorySize, SMEM_BYTES);
    cudaFuncSetAttribute(hop_tc,      cudaFuncAttributeMaxDynamicSharedMemorySize, SMEM_BYTES);

    zero_mean <<<(Bsz * Ss / 4) / 256, 256>>>();
    split_all <<<NALL / 256, 256>>>(x, W_in, sym_W, ops_W);

    gemm_z_tc   <<<dim3(Bsz / TILEM, Dm / 128), 256, SMEM_BYTES>>>(b_in);
    gemm_sym_tc <<<dim3(Bsz / TILEM, (Nn * Ss) / 128), 256, SMEM_BYTES>>>(sym);  // 4th: profiled
    router_kernel<<<Bsz / 4, 576>>>(router_W, router_b, progf);
    schedule_kernel<<<1, 512>>>();

    hop_tc<<<dim3(MAXT, Dm / 128), 256, SMEM_BYTES>>>(0, 0, ops_b);
    hop_tc<<<dim3(MAXT, Dm / 128), 256, SMEM_BYTES>>>(1, 1, ops_b);
    hop_tc<<<dim3(MAXT, Dm / 128), 256, SMEM_BYTES>>>(2, 0, ops_b);
    hop_tc<<<dim3(MAXT, Dm / 128), 256, SMEM_BYTES>>>(3, 1, ops_b);

    gather_out<<<(Bsz * Dm / 2) / 256, 256>>>(out);
}